// round 3
// baseline (speedup 1.0000x reference)
#include <cuda_runtime.h>
#include <math.h>

#define BH 32
#define NSEQ 4096
#define DDIM 64
#define MDIM 266
#define MPAD 272            // padded m (even, 68 float4)
#define ECOLS 65            // 64 v-cols + 1 ones-col (k_mean)
#define EPAD 68
#define PSTR 68             // padded floats per 64-float row (17 float4)
#define CTSTR 274           // CsT row stride in floats (even -> 8B-aligned u64 rows)
#define NORMALIZER 0.3535533905932738f   // 64^-0.25
#define DIAGC 0.0625f                    // 0.5 * 64^-0.5
#define KEPS 1e-4f
#define RATIO 0.06131393835f             // 266^-0.5

// packed fp32 FMA: acc.{lo,hi} += a.{lo,hi} * b.{lo,hi}
#define FMA2(acc, a, b) asm("fma.rn.f32x2 %0, %1, %2, %0;" : "+l"(acc) : "l"(a), "l"(b))

__device__ __forceinline__ float pairsum(unsigned long long v) {
    float lo, hi;
    asm("mov.b64 {%0,%1}, %2;" : "=f"(lo), "=f"(hi) : "l"(v));
    return lo + hi;
}

// ---------------- scratch (static device globals; no allocation) ----------
__device__ unsigned int g_stab_bits;
__device__ float g_C[BH * MDIM * ECOLS];                 // [bh][m][e]
__device__ float g_kdash[(size_t)BH * NSEQ * MPAD];      // raw k_dash (pads garbage, never read)
__device__ float g_qdash[(size_t)BH * NSEQ * MPAD];
__device__ float g_kdiag[BH * NSEQ];
__device__ float g_qdiag[BH * NSEQ];

// ordered-uint encoding for float atomicMax
__device__ __forceinline__ unsigned int fenc(float f) {
    unsigned int b = __float_as_uint(f);
    return (b & 0x80000000u) ? ~b : (b | 0x80000000u);
}
__device__ __forceinline__ float fdec(unsigned int u) {
    return (u & 0x80000000u) ? __uint_as_float(u & 0x7FFFFFFFu) : __uint_as_float(~u);
}

__global__ void init_kernel() {
    int i = blockIdx.x * blockDim.x + threadIdx.x;
    if (i == 0) g_stab_bits = 0u;
    int stride = gridDim.x * blockDim.x;
    for (int idx = i; idx < BH * MDIM * ECOLS; idx += stride) g_C[idx] = 0.0f;
}

// =======================================================================
// dash kernel: dash = NORMALIZER * (X @ P^T) -> global; diag -> global;
// if isK: global atomicMax of dash. f32x2 paired over d.
// grid BH*32 (128 rows each, 4 subtiles of 32), 544 threads.
// =======================================================================
__global__ void __launch_bounds__(544, 2) dash_kernel(const float* __restrict__ x,
                                                      const float* __restrict__ proj,
                                                      int isK) {
    extern __shared__ float sm[];
    float* ps = sm;                   // [272][68] padded proj (rows >=266 zero)
    float* xs = ps + MPAD * PSTR;     // [32][68]
    __shared__ unsigned int red;
    int tid = threadIdx.x;

    {
        const float4* p4 = (const float4*)proj;
        float4* ps4 = (float4*)ps;
        float4 z = make_float4(0.f, 0.f, 0.f, 0.f);
        for (int i = tid; i < MPAD * 16; i += 544) {
            int m = i >> 4, d4 = i & 15;
            ps4[m * 17 + d4] = (m < MDIM) ? p4[m * 16 + d4] : z;
        }
    }
    if (tid == 0) red = 0u;

    float* dashp = isK ? g_kdash : g_qdash;
    float* diagp = isK ? g_kdiag : g_qdiag;

    int bh = blockIdx.x >> 5;
    int row0b = (blockIdx.x & 31) * 128;
    const float* xbase = x + ((size_t)bh * NSEQ + row0b) * DDIM;
    float* dbase = dashp + ((size_t)bh * NSEQ + row0b) * MPAD;
    float* gdiag = diagp + bh * NSEQ + row0b;

    int tx = tid % 136;
    int ty = tid / 136;               // 0..3, 8 rows each
    int m0 = tx, m1 = tx + 136;
    float maxv = -INFINITY;
    const ulonglong2* psU = (const ulonglong2*)ps;
    const ulonglong2* xsU = (const ulonglong2*)xs;

    for (int s = 0; s < 4; s++) {
        __syncthreads();
        {   // load 32x64 tile
            const float4* s4 = (const float4*)(xbase + (size_t)s * 32 * DDIM);
            float4* t4 = (float4*)xs;
            for (int i = tid; i < 512; i += 544) {
                int r = i >> 4, d4 = i & 15;
                t4[r * 17 + d4] = s4[i];
            }
        }
        __syncthreads();
        if (tid < 32) {
            const float4* xr = (const float4*)xs + tid * 17;
            float ssum = 0.f;
#pragma unroll
            for (int d4 = 0; d4 < 16; d4++) {
                float4 kv = xr[d4];
                ssum += kv.x * kv.x + kv.y * kv.y + kv.z * kv.z + kv.w * kv.w;
            }
            gdiag[s * 32 + tid] = DIAGC * ssum;
        }
        unsigned long long acc[8][2];
#pragma unroll
        for (int r = 0; r < 8; r++) { acc[r][0] = 0ULL; acc[r][1] = 0ULL; }
#pragma unroll
        for (int d4 = 0; d4 < 16; d4++) {
            ulonglong2 pa = psU[m0 * 17 + d4];
            ulonglong2 pb = psU[m1 * 17 + d4];
#pragma unroll
            for (int r = 0; r < 8; r++) {
                ulonglong2 kd = xsU[(ty * 8 + r) * 17 + d4];
                FMA2(acc[r][0], kd.x, pa.x);
                FMA2(acc[r][0], kd.y, pa.y);
                FMA2(acc[r][1], kd.x, pb.x);
                FMA2(acc[r][1], kd.y, pb.y);
            }
        }
        float* drow = dbase + (size_t)(s * 32) * MPAD;
#pragma unroll
        for (int r = 0; r < 8; r++) {
            int row = ty * 8 + r;
            float d0 = NORMALIZER * pairsum(acc[r][0]);
            float d1 = NORMALIZER * pairsum(acc[r][1]);
            drow[row * MPAD + m0] = d0;
            drow[row * MPAD + m1] = d1;       // m1>=266 writes pads; never read
            maxv = fmaxf(maxv, d0);
            if (m1 < MDIM) maxv = fmaxf(maxv, d1);
        }
    }
    if (isK) {
        __syncthreads();
        atomicMax(&red, fenc(maxv));
        __syncthreads();
        if (tid == 0) atomicMax(&g_stab_bits, red);
    }
}

// =======================================================================
// context kernel: kp = c1*(exp(kdash - diag - stab)+eps); C += kp^T @ [V|1]
// grid BH*8 (512 rows each, 16 subtiles of 32), 512 threads.
// =======================================================================
__global__ void __launch_bounds__(512, 1) context_kernel(const float* __restrict__ vv) {
    extern __shared__ float sm[];
    float* Cl = sm;                   // [272][68]
    float* kp = Cl + MPAD * EPAD;     // [32][272]
    float* vs = kp + 32 * MPAD;       // [32][68]
    int tid = threadIdx.x;
    for (int i = tid; i < MPAD * EPAD; i += 512) Cl[i] = 0.f;

    int bh = blockIdx.x >> 3;
    int row0b = (blockIdx.x & 7) * 512;
    const float* dbase = g_kdash + ((size_t)bh * NSEQ + row0b) * MPAD;
    const float* diagb = g_kdiag + bh * NSEQ + row0b;
    const float* vbase = vv + ((size_t)bh * NSEQ + row0b) * DDIM;
    const float stab = fdec(*(volatile unsigned int*)&g_stab_bits);
    const float c1 = RATIO / (float)NSEQ;

    float4* Cl4 = (float4*)Cl;
    const float4* kp4 = (const float4*)kp;
    const float4* vs4 = (const float4*)vs;

    for (int s = 0; s < 16; s++) {
        __syncthreads();
        {   // V tile (each thread exactly one float4)
            const float4* s4 = (const float4*)(vbase + (size_t)s * 32 * DDIM);
            float4* t4 = (float4*)vs;
            int i = tid;
            if (i < 512) {
                int r = i >> 4, d4 = i & 15;
                t4[r * 17 + d4] = s4[i];
            }
        }
        {   // kp with exp (16 threads per row)
            int r = tid >> 4, part = tid & 15;
            const float* drow = dbase + (size_t)(s * 32 + r) * MPAD;
            float dg = diagb[s * 32 + r] + stab;
            for (int m = part; m < MPAD; m += 16) {
                float val = 0.f;
                if (m < MDIM) val = c1 * (__expf(drow[m] - dg) + KEPS);
                kp[r * MPAD + m] = val;
            }
            if (part == 0) {
                vs[r * PSTR + 64] = 1.0f;     // ones column -> k_mean
                vs[r * PSTR + 65] = 0.f;
                vs[r * PSTR + 66] = 0.f;
                vs[r * PSTR + 67] = 0.f;
            }
        }
        __syncthreads();

        // outer product: Cl[m][e] += sum_r kp[r][m] * vs[r][e]  (4m x 4e tiles)
        for (int t = tid; t < 17 * 68; t += 512) {
            int eg = t / 68, mg = t - eg * 68;
            float4 a0 = Cl4[(mg * 4 + 0) * 17 + eg];
            float4 a1 = Cl4[(mg * 4 + 1) * 17 + eg];
            float4 a2 = Cl4[(mg * 4 + 2) * 17 + eg];
            float4 a3 = Cl4[(mg * 4 + 3) * 17 + eg];
#pragma unroll 4
            for (int r = 0; r < 32; r++) {
                float4 kq = kp4[r * 68 + mg];
                float4 vq = vs4[r * 17 + eg];
                a0.x = fmaf(kq.x, vq.x, a0.x); a0.y = fmaf(kq.x, vq.y, a0.y);
                a0.z = fmaf(kq.x, vq.z, a0.z); a0.w = fmaf(kq.x, vq.w, a0.w);
                a1.x = fmaf(kq.y, vq.x, a1.x); a1.y = fmaf(kq.y, vq.y, a1.y);
                a1.z = fmaf(kq.y, vq.z, a1.z); a1.w = fmaf(kq.y, vq.w, a1.w);
                a2.x = fmaf(kq.z, vq.x, a2.x); a2.y = fmaf(kq.z, vq.y, a2.y);
                a2.z = fmaf(kq.z, vq.z, a2.z); a2.w = fmaf(kq.z, vq.w, a2.w);
                a3.x = fmaf(kq.w, vq.x, a3.x); a3.y = fmaf(kq.w, vq.y, a3.y);
                a3.z = fmaf(kq.w, vq.z, a3.z); a3.w = fmaf(kq.w, vq.w, a3.w);
            }
            Cl4[(mg * 4 + 0) * 17 + eg] = a0;
            Cl4[(mg * 4 + 1) * 17 + eg] = a1;
            Cl4[(mg * 4 + 2) * 17 + eg] = a2;
            Cl4[(mg * 4 + 3) * 17 + eg] = a3;
        }
    }
    __syncthreads();
    float* gC = g_C + (size_t)bh * MDIM * ECOLS;
    for (int idx = tid; idx < MDIM * ECOLS; idx += 512) {
        int m = idx / ECOLS, e = idx - m * ECOLS;
        atomicAdd(&gC[idx], Cl[m * EPAD + e]);
    }
}

// =======================================================================
// out kernel: qp = exp-transform(qdash, per-row stab); out = D_inv * qp @ C
// GEMM uses f32x2 paired over m against transposed C (CsT).
// grid BH*32 (128 rows each, 4 subtiles of 32), 256 threads, 2 blocks/SM.
// =======================================================================
__global__ void __launch_bounds__(256, 2) out_kernel(float* __restrict__ out) {
    extern __shared__ float sm[];
    float* CsT    = sm;                       // [65][274]  e-major
    float* qp     = CsT + 65 * CTSTR;         // [32][272]
    float* stab_s = qp + 32 * MPAD;           // 32
    float* den    = stab_s + 32;              // 32
    int tid = threadIdx.x;
    int bh = blockIdx.x >> 5;
    int row0b = (blockIdx.x & 31) * 128;

    {   // transposed load of g_C + zero pads m in [266,274)
        const float* gC = g_C + (size_t)bh * MDIM * ECOLS;
        for (int i = tid; i < MDIM * ECOLS; i += 256) {
            int m = i / ECOLS, e = i - m * ECOLS;
            CsT[e * CTSTR + m] = gC[i];
        }
        for (int t = tid; t < 65 * 8; t += 256) {
            int e = t >> 3, m = MDIM + (t & 7);
            CsT[e * CTSTR + m] = 0.f;
        }
    }
    const float* dbase = g_qdash + ((size_t)bh * NSEQ + row0b) * MPAD;
    const float* diagb = g_qdiag + bh * NSEQ + row0b;
    float* obase = out + ((size_t)bh * NSEQ + row0b) * DDIM;

    const unsigned long long* CsTU = (const unsigned long long*)CsT;
    const unsigned long long* qpU  = (const unsigned long long*)qp;
    int eg = tid & 31, rg = tid >> 5;         // rg warp-uniform

    for (int s = 0; s < 4; s++) {
        __syncthreads();
        {   // raw qdash into smem
            int r = tid >> 3, part = tid & 7;
            const float* drow = dbase + (size_t)(s * 32 + r) * MPAD;
            for (int m = part; m < MPAD; m += 8) qp[r * MPAD + m] = drow[m];
        }
        __syncthreads();
        {   // per-row max over valid m
            int r = tid >> 3, part = tid & 7;
            float mv = -INFINITY;
            for (int m = part; m < MDIM; m += 8) mv = fmaxf(mv, qp[r * MPAD + m]);
            mv = fmaxf(mv, __shfl_xor_sync(0xffffffffu, mv, 1));
            mv = fmaxf(mv, __shfl_xor_sync(0xffffffffu, mv, 2));
            mv = fmaxf(mv, __shfl_xor_sync(0xffffffffu, mv, 4));
            if (part == 0) stab_s[r] = mv;
        }
        __syncthreads();
        {   // exp transform (pads -> 0)
            int r = tid >> 3, part = tid & 7;
            float dg = diagb[s * 32 + r] + stab_s[r];
            for (int m = part; m < MPAD; m += 8) {
                float val = 0.f;
                if (m < MDIM) val = RATIO * (__expf(qp[r * MPAD + m] - dg) + KEPS);
                qp[r * MPAD + m] = val;
            }
        }
        __syncthreads();
        {   // denominator: qp row . CsT[e=64] (pads are 0 on both sides)
            int r = tid >> 3, part = tid & 7;
            float dd = 0.f;
            for (int m = part; m < MPAD; m += 8) dd += qp[r * MPAD + m] * CsT[64 * CTSTR + m];
            dd += __shfl_xor_sync(0xffffffffu, dd, 1);
            dd += __shfl_xor_sync(0xffffffffu, dd, 2);
            dd += __shfl_xor_sync(0xffffffffu, dd, 4);
            if (part == 0) den[r] = dd;
        }
        __syncthreads();
        {   // f32x2 GEMM: 4 rows x 2 e per thread, paired over m
            unsigned long long a0[4], a1[4];
#pragma unroll
            for (int j = 0; j < 4; j++) { a0[j] = 0ULL; a1[j] = 0ULL; }
            const unsigned long long* c0 = CsTU + (size_t)(2 * eg) * 137;
            const unsigned long long* c1p = CsTU + (size_t)(2 * eg + 1) * 137;
            const unsigned long long* q0 = qpU + (size_t)(rg * 4) * 136;
#pragma unroll 2
            for (int mp = 0; mp < 136; mp++) {
                unsigned long long cb0 = c0[mp], cb1 = c1p[mp];
#pragma unroll
                for (int j = 0; j < 4; j++) {
                    unsigned long long qa = q0[j * 136 + mp];
                    FMA2(a0[j], qa, cb0);
                    FMA2(a1[j], qa, cb1);
                }
            }
#pragma unroll
            for (int j = 0; j < 4; j++) {
                int r = rg * 4 + j;
                float di = 1.0f / den[r];
                float2 o;
                o.x = pairsum(a0[j]) * di;
                o.y = pairsum(a1[j]) * di;
                ((float2*)(obase + (size_t)(s * 32 + r) * DDIM))[eg] = o;
            }
        }
    }
}

// =======================================================================
extern "C" void kernel_launch(void* const* d_in, const int* in_sizes, int n_in,
                              void* d_out, int out_size) {
    int pidx = -1;
    for (int i = 0; i < n_in; i++) if (in_sizes[i] == MDIM * DDIM) pidx = i;
    const float* rest[3] = {nullptr, nullptr, nullptr};
    int rc = 0;
    for (int i = 0; i < n_in && rc < 3; i++) {
        if (i == pidx) continue;
        rest[rc++] = (const float*)d_in[i];
    }
    const float* q = rest[0];
    const float* k = rest[1];
    const float* v = rest[2];
    const float* proj = (const float*)d_in[pidx];
    float* out = (float*)d_out;

    int smA = (MPAD * PSTR + 32 * PSTR + 16) * (int)sizeof(float);                  // ~83 KB
    int smB = (MPAD * EPAD + 32 * MPAD + 32 * PSTR + 16) * (int)sizeof(float);      // ~118 KB
    int smC = (65 * CTSTR + 32 * MPAD + 80) * (int)sizeof(float);                   // ~106 KB

    cudaFuncSetAttribute(dash_kernel,    cudaFuncAttributeMaxDynamicSharedMemorySize, smA);
    cudaFuncSetAttribute(context_kernel, cudaFuncAttributeMaxDynamicSharedMemorySize, smB);
    cudaFuncSetAttribute(out_kernel,     cudaFuncAttributeMaxDynamicSharedMemorySize, smC);

    init_kernel<<<256, 256>>>();
    dash_kernel<<<BH * 32, 544, smA>>>(k, proj, 1);
    dash_kernel<<<BH * 32, 544, smA>>>(q, proj, 0);
    context_kernel<<<BH * 8, 512, smB>>>(v);
    out_kernel<<<BH * 32, 256, smC>>>(out);
}

// round 4
// speedup vs baseline: 1.1372x; 1.1372x over previous
#include <cuda_runtime.h>
#include <math.h>

#define BH 32
#define NSEQ 4096
#define DDIM 64
#define MDIM 266
#define MPAD 272            // 4 stripes of 68
#define MSTRIPE 68
#define ECOLS 65            // 64 v-cols + 1 ones-col (k_mean)
#define CTSTR 276           // CsT row stride floats (69 f4, 69%8=5 -> conflict-free)
#define NORMALIZER 0.3535533905932738f   // 64^-0.25
#define DIAGC 0.0625f                    // 0.5 * 64^-0.5
#define KEPS 1e-4f
#define RATIO 0.06131393835f             // 266^-0.5

// packed fp32 FMA: acc.{lo,hi} += a.{lo,hi} * b.{lo,hi}
#define FMA2(acc, a, b) asm("fma.rn.f32x2 %0, %1, %2, %0;" : "+l"(acc) : "l"(a), "l"(b))

__device__ __forceinline__ float pairsum(unsigned long long v) {
    float lo, hi;
    asm("mov.b64 {%0,%1}, %2;" : "=f"(lo), "=f"(hi) : "l"(v));
    return lo + hi;
}

// ---------------- scratch (static device globals; no allocation) ----------
__device__ unsigned int g_stab_bits;
__device__ float g_C[BH * MDIM * ECOLS];                 // [bh][m][e]
__device__ float g_kdash[(size_t)BH * NSEQ * MPAD];
__device__ float g_qdash[(size_t)BH * NSEQ * MPAD];
__device__ float g_kdiag[BH * NSEQ];
__device__ float g_qdiag[BH * NSEQ];

__device__ __forceinline__ unsigned int fenc(float f) {
    unsigned int b = __float_as_uint(f);
    return (b & 0x80000000u) ? ~b : (b | 0x80000000u);
}
__device__ __forceinline__ float fdec(unsigned int u) {
    return (u & 0x80000000u) ? __uint_as_float(u & 0x7FFFFFFFu) : __uint_as_float(~u);
}

__global__ void init_kernel() {
    int i = blockIdx.x * blockDim.x + threadIdx.x;
    if (i == 0) g_stab_bits = 0u;
    int stride = gridDim.x * blockDim.x;
    for (int idx = i; idx < BH * MDIM * ECOLS; idx += stride) g_C[idx] = 0.0f;
}

// =======================================================================
// dash: dash = NORMALIZER * (X @ P^T) for one 68-m stripe, 128 rows.
// grid (32 rowchunk, 4 stripe, 32 bh), 272 threads.
// thread: 4 m (stride 17) x 2 rows, f32x2 over d.
// =======================================================================
__global__ void __launch_bounds__(272, 3) dash_kernel(const float* __restrict__ x,
                                                      const float* __restrict__ proj,
                                                      int isK) {
    extern __shared__ float sm[];
    float* ps = sm;                     // [68][68] (17 f4/row, last f4 pad)
    float* xs = ps + MSTRIPE * 68;      // [32][68]
    __shared__ unsigned int red;
    int tid = threadIdx.x;
    int bh = blockIdx.z;
    int mbase = blockIdx.y * MSTRIPE;
    int row0b = blockIdx.x * 128;

    {   // proj stripe -> smem (zero rows for m >= MDIM)
        const float4* p4 = (const float4*)proj;
        float4* ps4 = (float4*)ps;
        float4 z = make_float4(0.f, 0.f, 0.f, 0.f);
        for (int i = tid; i < MSTRIPE * 16; i += 272) {
            int ml = i >> 4, d4 = i & 15;
            int m = mbase + ml;
            ps4[ml * 17 + d4] = (m < MDIM) ? p4[m * 16 + d4] : z;
        }
    }
    if (tid == 0) red = 0u;

    float* dashp = isK ? g_kdash : g_qdash;
    float* diagp = isK ? g_kdiag : g_qdiag;
    const float* xbase = x + ((size_t)bh * NSEQ + row0b) * DDIM;
    float* dbase = dashp + ((size_t)bh * NSEQ + row0b) * MPAD;
    float* gdiag = diagp + bh * NSEQ + row0b;

    int ml0 = tid % 17;          // m-lane; m's = ml0 + 17*i
    int rg = tid / 17;           // 0..15 -> rows 2rg, 2rg+1
    const ulonglong2* psU = (const ulonglong2*)ps;
    const ulonglong2* xsU = (const ulonglong2*)xs;
    float maxv = -INFINITY;

    for (int s = 0; s < 4; s++) {
        __syncthreads();
        {   // 32x64 x-tile
            const float4* s4 = (const float4*)(xbase + (size_t)s * 32 * DDIM);
            float4* t4 = (float4*)xs;
            for (int i = tid; i < 512; i += 272) {
                int r = i >> 4, d4 = i & 15;
                t4[r * 17 + d4] = s4[i];
            }
        }
        __syncthreads();
        if (tid < 32) {          // diag for this subtile (stripe 0 writes; all write same value, benign)
            const float4* xr = (const float4*)xs + tid * 17;
            float ssum = 0.f;
#pragma unroll
            for (int d4 = 0; d4 < 16; d4++) {
                float4 kv = xr[d4];
                ssum += kv.x * kv.x + kv.y * kv.y + kv.z * kv.z + kv.w * kv.w;
            }
            gdiag[s * 32 + tid] = DIAGC * ssum;
        }
        unsigned long long acc[2][4];
#pragma unroll
        for (int j = 0; j < 2; j++)
#pragma unroll
            for (int i = 0; i < 4; i++) acc[j][i] = 0ULL;
#pragma unroll
        for (int d4 = 0; d4 < 16; d4++) {
            ulonglong2 pa0 = psU[(ml0 + 0)  * 17 + d4];
            ulonglong2 pa1 = psU[(ml0 + 17) * 17 + d4];
            ulonglong2 pa2 = psU[(ml0 + 34) * 17 + d4];
            ulonglong2 pa3 = psU[(ml0 + 51) * 17 + d4];
#pragma unroll
            for (int j = 0; j < 2; j++) {
                ulonglong2 xa = xsU[(rg * 2 + j) * 17 + d4];
                FMA2(acc[j][0], xa.x, pa0.x); FMA2(acc[j][0], xa.y, pa0.y);
                FMA2(acc[j][1], xa.x, pa1.x); FMA2(acc[j][1], xa.y, pa1.y);
                FMA2(acc[j][2], xa.x, pa2.x); FMA2(acc[j][2], xa.y, pa2.y);
                FMA2(acc[j][3], xa.x, pa3.x); FMA2(acc[j][3], xa.y, pa3.y);
            }
        }
#pragma unroll
        for (int j = 0; j < 2; j++) {
            int row = rg * 2 + j;
            float* drow = dbase + (size_t)(s * 32 + row) * MPAD + mbase;
#pragma unroll
            for (int i = 0; i < 4; i++) {
                float dv = NORMALIZER * pairsum(acc[j][i]);
                drow[ml0 + 17 * i] = dv;
                if (mbase + ml0 + 17 * i < MDIM) maxv = fmaxf(maxv, dv);
            }
        }
    }
    if (isK) {
        __syncthreads();
        atomicMax(&red, fenc(maxv));
        __syncthreads();
        if (tid == 0) atomicMax(&g_stab_bits, red);
    }
}

// =======================================================================
// context: kp = c1*(exp(kdash-diag-stab)+eps) for one 68-m stripe;
// Cl[68m][68e] += kp^T @ [V|1] over 512 rows; atomicAdd to g_C.
// grid (8 rowchunk, 4 stripe, 32 bh), 256 threads.
// =======================================================================
__global__ void __launch_bounds__(256, 4) context_kernel(const float* __restrict__ vv) {
    extern __shared__ float sm[];
    float* Cl = sm;                      // [68][68]
    float* kp = Cl + MSTRIPE * 68;       // [32][68]
    float* vs = kp + 32 * 68;            // [32][68]
    __shared__ float diag_s[32];
    int tid = threadIdx.x;
    int bh = blockIdx.z;
    int mbase = blockIdx.y * MSTRIPE;
    int row0b = blockIdx.x * 512;

    for (int i = tid; i < MSTRIPE * 68; i += 256) Cl[i] = 0.f;

    const float* dbase = g_kdash + ((size_t)bh * NSEQ + row0b) * MPAD;
    const float* diagb = g_kdiag + bh * NSEQ + row0b;
    const float* vbase = vv + ((size_t)bh * NSEQ + row0b) * DDIM;
    const float stab = fdec(*(volatile unsigned int*)&g_stab_bits);
    const float c1 = RATIO / (float)NSEQ;

    float4* Cl4 = (float4*)Cl;
    const float4* kp4 = (const float4*)kp;
    const float4* vs4 = (const float4*)vs;

    for (int s = 0; s < 16; s++) {
        __syncthreads();
        {   // V tile + ones column
            const float4* s4 = (const float4*)(vbase + (size_t)s * 32 * DDIM);
            float4* t4 = (float4*)vs;
            for (int t = tid; t < 544; t += 256) {
                int r = t / 17, e4 = t % 17;
                t4[r * 17 + e4] = (e4 < 16) ? s4[r * 16 + e4]
                                            : make_float4(1.f, 0.f, 0.f, 0.f);
            }
        }
        if (tid < 32) diag_s[tid] = diagb[s * 32 + tid] + stab;
        __syncthreads();
        {   // kp stripe with exp
            for (int t = tid; t < 544; t += 256) {
                int r = t / 17, m4 = t % 17;
                const float* drow = dbase + (size_t)(s * 32 + r) * MPAD + mbase;
                float4 dd = *(const float4*)(drow + m4 * 4);
                float dg = diag_s[r];
                int m = mbase + m4 * 4;
                float4 o;
                o.x = (m + 0 < MDIM) ? c1 * (__expf(dd.x - dg) + KEPS) : 0.f;
                o.y = (m + 1 < MDIM) ? c1 * (__expf(dd.y - dg) + KEPS) : 0.f;
                o.z = (m + 2 < MDIM) ? c1 * (__expf(dd.z - dg) + KEPS) : 0.f;
                o.w = (m + 3 < MDIM) ? c1 * (__expf(dd.w - dg) + KEPS) : 0.f;
                ((float4*)kp)[r * 17 + m4] = o;
            }
        }
        __syncthreads();
        // outer product: 17x17 tiles of 4m x 4e; eg fast -> conflict-free Cl
        for (int t = tid; t < 289; t += 256) {
            int eg = t % 17, mg = t / 17;
            float4 a0 = Cl4[(mg * 4 + 0) * 17 + eg];
            float4 a1 = Cl4[(mg * 4 + 1) * 17 + eg];
            float4 a2 = Cl4[(mg * 4 + 2) * 17 + eg];
            float4 a3 = Cl4[(mg * 4 + 3) * 17 + eg];
#pragma unroll 4
            for (int r = 0; r < 32; r++) {
                float4 kq = kp4[r * 17 + mg];
                float4 vq = vs4[r * 17 + eg];
                a0.x = fmaf(kq.x, vq.x, a0.x); a0.y = fmaf(kq.x, vq.y, a0.y);
                a0.z = fmaf(kq.x, vq.z, a0.z); a0.w = fmaf(kq.x, vq.w, a0.w);
                a1.x = fmaf(kq.y, vq.x, a1.x); a1.y = fmaf(kq.y, vq.y, a1.y);
                a1.z = fmaf(kq.y, vq.z, a1.z); a1.w = fmaf(kq.y, vq.w, a1.w);
                a2.x = fmaf(kq.z, vq.x, a2.x); a2.y = fmaf(kq.z, vq.y, a2.y);
                a2.z = fmaf(kq.z, vq.z, a2.z); a2.w = fmaf(kq.z, vq.w, a2.w);
                a3.x = fmaf(kq.w, vq.x, a3.x); a3.y = fmaf(kq.w, vq.y, a3.y);
                a3.z = fmaf(kq.w, vq.z, a3.z); a3.w = fmaf(kq.w, vq.w, a3.w);
            }
            Cl4[(mg * 4 + 0) * 17 + eg] = a0;
            Cl4[(mg * 4 + 1) * 17 + eg] = a1;
            Cl4[(mg * 4 + 2) * 17 + eg] = a2;
            Cl4[(mg * 4 + 3) * 17 + eg] = a3;
        }
    }
    __syncthreads();
    float* gC = g_C + (size_t)bh * MDIM * ECOLS;
    for (int idx = tid; idx < MSTRIPE * ECOLS; idx += 256) {
        int ml = idx / ECOLS, e = idx - ml * ECOLS;
        int m = mbase + ml;
        if (m < MDIM) atomicAdd(&gC[m * ECOLS + e], Cl[ml * 68 + e]);
    }
}

// =======================================================================
// out: qp = exp-transform(qdash, per-row stab); out = D_inv * qp @ C.
// e split in halves; CsT[e][m] transposed, stride 276 (conflict-free).
// grid (32 rowchunk, 2 ehalf, 32 bh), 256 threads.
// =======================================================================
__global__ void __launch_bounds__(256, 3) out_kernel(float* __restrict__ out) {
    extern __shared__ float sm[];
    float* CsT    = sm;                       // [33][276]: 32 e-rows + den col row
    float* qp     = CsT + 33 * CTSTR;         // [32][272]
    float* stab_s = qp + 32 * MPAD;           // 32
    float* den    = stab_s + 32;              // 32
    int tid = threadIdx.x;
    int bh = blockIdx.z;
    int h = blockIdx.y;                       // e-half
    int row0b = blockIdx.x * 128;

    {   // transposed C load (+ den col as row 32), zero m-pads
        const float* gC = g_C + (size_t)bh * MDIM * ECOLS;
        for (int el = 0; el < 33; el++) {
            int e = (el < 32) ? h * 32 + el : 64;
            const float* gCe = gC + e;
            for (int m = tid; m < MDIM; m += 256) CsT[el * CTSTR + m] = gCe[m * ECOLS];
            for (int m = MDIM + tid; m < CTSTR; m += 256) CsT[el * CTSTR + m] = 0.f;
        }
    }
    const float* dbase = g_qdash + ((size_t)bh * NSEQ + row0b) * MPAD;
    const float* diagb = g_qdiag + bh * NSEQ + row0b;
    float* obase = out + ((size_t)bh * NSEQ + row0b) * DDIM + h * 32;

    const ulonglong2* CsU = (const ulonglong2*)CsT;   // row stride 69
    const ulonglong2* qpU = (const ulonglong2*)qp;    // row stride 68
    int eg = tid & 31, rg = tid >> 5;

    for (int s = 0; s < 4; s++) {
        __syncthreads();
        {   // raw qdash -> qp (full m)
            float4* qp4 = (float4*)qp;
            for (int t = tid; t < 2176; t += 256) {
                int r = t / 68, m4 = t % 68;
                qp4[r * 68 + m4] = *(const float4*)(dbase + (size_t)(s * 32 + r) * MPAD + m4 * 4);
            }
        }
        __syncthreads();
        {   // per-row max over valid m
            int r = tid >> 3, part = tid & 7;
            float mv = -INFINITY;
            for (int m = part; m < MDIM; m += 8) mv = fmaxf(mv, qp[r * MPAD + m]);
            mv = fmaxf(mv, __shfl_xor_sync(0xffffffffu, mv, 1));
            mv = fmaxf(mv, __shfl_xor_sync(0xffffffffu, mv, 2));
            mv = fmaxf(mv, __shfl_xor_sync(0xffffffffu, mv, 4));
            if (part == 0) stab_s[r] = mv;
        }
        __syncthreads();
        {   // exp transform (pads -> 0)
            int r = tid >> 3, part = tid & 7;
            float dg = diagb[s * 32 + r] + stab_s[r];
            for (int m = part; m < MPAD; m += 8) {
                float val = 0.f;
                if (m < MDIM) val = RATIO * (__expf(qp[r * MPAD + m] - dg) + KEPS);
                qp[r * MPAD + m] = val;
            }
        }
        __syncthreads();
        {   // denominator: qp row . CsT row 32
            int r = tid >> 3, part = tid & 7;
            const float* dc = CsT + 32 * CTSTR;
            float dd = 0.f;
            for (int m = part; m < MPAD; m += 8) dd += qp[r * MPAD + m] * dc[m];
            dd += __shfl_xor_sync(0xffffffffu, dd, 1);
            dd += __shfl_xor_sync(0xffffffffu, dd, 2);
            dd += __shfl_xor_sync(0xffffffffu, dd, 4);
            if (part == 0) den[r] = dd;
        }
        __syncthreads();
        {   // GEMM: lane = e-row, warp = 4 q-rows, f32x2 over m
            unsigned long long a0 = 0ULL, a1 = 0ULL, a2 = 0ULL, a3 = 0ULL;
            const ulonglong2* crow = CsU + (size_t)eg * 69;
            const ulonglong2* q0 = qpU + (size_t)(rg * 4) * 68;
#pragma unroll 4
            for (int qd = 0; qd < 68; qd++) {
                ulonglong2 c = crow[qd];
                ulonglong2 qa = q0[qd];
                ulonglong2 qb = q0[68 + qd];
                ulonglong2 qc = q0[136 + qd];
                ulonglong2 qe = q0[204 + qd];
                FMA2(a0, qa.x, c.x); FMA2(a0, qa.y, c.y);
                FMA2(a1, qb.x, c.x); FMA2(a1, qb.y, c.y);
                FMA2(a2, qc.x, c.x); FMA2(a2, qc.y, c.y);
                FMA2(a3, qe.x, c.x); FMA2(a3, qe.y, c.y);
            }
            int r0 = rg * 4;
            obase[(size_t)(s * 32 + r0 + 0) * DDIM + eg] = pairsum(a0) / den[r0 + 0];
            obase[(size_t)(s * 32 + r0 + 1) * DDIM + eg] = pairsum(a1) / den[r0 + 1];
            obase[(size_t)(s * 32 + r0 + 2) * DDIM + eg] = pairsum(a2) / den[r0 + 2];
            obase[(size_t)(s * 32 + r0 + 3) * DDIM + eg] = pairsum(a3) / den[r0 + 3];
        }
    }
}

// =======================================================================
extern "C" void kernel_launch(void* const* d_in, const int* in_sizes, int n_in,
                              void* d_out, int out_size) {
    int pidx = -1;
    for (int i = 0; i < n_in; i++) if (in_sizes[i] == MDIM * DDIM) pidx = i;
    const float* rest[3] = {nullptr, nullptr, nullptr};
    int rc = 0;
    for (int i = 0; i < n_in && rc < 3; i++) {
        if (i == pidx) continue;
        rest[rc++] = (const float*)d_in[i];
    }
    const float* q = rest[0];
    const float* k = rest[1];
    const float* v = rest[2];
    const float* proj = (const float*)d_in[pidx];
    float* out = (float*)d_out;

    int smA = (MSTRIPE * 68 + 32 * 68) * (int)sizeof(float);               // ~27 KB
    int smB = (MSTRIPE * 68 + 32 * 68 + 32 * 68) * (int)sizeof(float);     // ~36 KB
    int smC = (33 * CTSTR + 32 * MPAD + 64) * (int)sizeof(float);          // ~71.5 KB

    cudaFuncSetAttribute(dash_kernel,    cudaFuncAttributeMaxDynamicSharedMemorySize, smA);
    cudaFuncSetAttribute(context_kernel, cudaFuncAttributeMaxDynamicSharedMemorySize, smB);
    cudaFuncSetAttribute(out_kernel,     cudaFuncAttributeMaxDynamicSharedMemorySize, smC);

    init_kernel<<<256, 256>>>();
    dash_kernel<<<dim3(32, 4, 32), 272, smA>>>(k, proj, 1);
    dash_kernel<<<dim3(32, 4, 32), 272, smA>>>(q, proj, 0);
    context_kernel<<<dim3(8, 4, 32), 256, smB>>>(v);
    out_kernel<<<dim3(32, 2, 32), 256, smC>>>(out);
}

// round 6
// speedup vs baseline: 1.3487x; 1.1860x over previous
#include <cuda_runtime.h>
#include <math.h>

#define BH 32
#define NSEQ 4096
#define DDIM 64
#define MDIM 266
#define MPAD 272            // 4 stripes of 68
#define MSTRIPE 68
#define ECOLS 65            // 64 v-cols + 1 ones-col (k_mean)
#define EROWS 68            // g_CT rows (65 used, 3 pad)
#define CTSTR 276           // CsT row stride floats (69 f4, 69%8=5 -> conflict-free)
#define NORMALIZER 0.3535533905932738f   // 64^-0.25
#define DIAGC 0.0625f                    // 0.5 * 64^-0.5
#define KEPS 1e-4f
#define RATIO 0.06131393835f             // 266^-0.5

// packed fp32 FMA: acc.{lo,hi} += a.{lo,hi} * b.{lo,hi}
#define FMA2(acc, a, b) asm("fma.rn.f32x2 %0, %1, %2, %0;" : "+l"(acc) : "l"(a), "l"(b))

__device__ __forceinline__ float pairsum(unsigned long long v) {
    float lo, hi;
    asm("mov.b64 {%0,%1}, %2;" : "=f"(lo), "=f"(hi) : "l"(v));
    return lo + hi;
}
__device__ __forceinline__ void unpack2(unsigned long long v, float& lo, float& hi) {
    asm("mov.b64 {%0,%1}, %2;" : "=f"(lo), "=f"(hi) : "l"(v));
}
__device__ __forceinline__ unsigned long long dupf(float x) {
    unsigned long long r;
    asm("mov.b64 %0, {%1,%1};" : "=l"(r) : "f"(x));
    return r;
}

// ---------------- scratch (static device globals; no allocation) ----------
__device__ unsigned int g_stab_bits;
__device__ float g_CT[(size_t)BH * EROWS * MPAD];        // [bh][e][m] transposed context
__device__ float g_kdash[(size_t)BH * NSEQ * MPAD];
__device__ float g_qdash[(size_t)BH * NSEQ * MPAD];
__device__ float g_kdiag[BH * NSEQ];
__device__ float g_qdiag[BH * NSEQ];

__device__ __forceinline__ unsigned int fenc(float f) {
    unsigned int b = __float_as_uint(f);
    return (b & 0x80000000u) ? ~b : (b | 0x80000000u);
}
__device__ __forceinline__ float fdec(unsigned int u) {
    return (u & 0x80000000u) ? __uint_as_float(u & 0x7FFFFFFFu) : __uint_as_float(~u);
}

__global__ void init_kernel() {
    int i = blockIdx.x * blockDim.x + threadIdx.x;
    if (i == 0) g_stab_bits = 0u;
    int stride = gridDim.x * blockDim.x;
    for (size_t idx = i; idx < (size_t)BH * EROWS * MPAD; idx += stride) g_CT[idx] = 0.0f;
}

// =======================================================================
// dash: dash = NORMALIZER * (X @ P^T) for one 68-m stripe, 128 rows.
// grid (32 rowchunk, 4 stripe, 32 bh), 272 threads.
// =======================================================================
__global__ void __launch_bounds__(272, 3) dash_kernel(const float* __restrict__ x,
                                                      const float* __restrict__ proj,
                                                      int isK) {
    extern __shared__ float sm[];
    float* ps = sm;                     // [68][68]
    float* xs = ps + MSTRIPE * 68;      // [32][68]
    __shared__ unsigned int red;
    int tid = threadIdx.x;
    int bh = blockIdx.z;
    int mbase = blockIdx.y * MSTRIPE;
    int row0b = blockIdx.x * 128;

    {
        const float4* p4 = (const float4*)proj;
        float4* ps4 = (float4*)ps;
        float4 z = make_float4(0.f, 0.f, 0.f, 0.f);
        for (int i = tid; i < MSTRIPE * 16; i += 272) {
            int ml = i >> 4, d4 = i & 15;
            int m = mbase + ml;
            ps4[ml * 17 + d4] = (m < MDIM) ? p4[m * 16 + d4] : z;
        }
    }
    if (tid == 0) red = 0u;

    float* dashp = isK ? g_kdash : g_qdash;
    float* diagp = isK ? g_kdiag : g_qdiag;
    const float* xbase = x + ((size_t)bh * NSEQ + row0b) * DDIM;
    float* dbase = dashp + ((size_t)bh * NSEQ + row0b) * MPAD;
    float* gdiag = diagp + bh * NSEQ + row0b;

    int ml0 = tid % 17;
    int rg = tid / 17;
    const ulonglong2* psU = (const ulonglong2*)ps;
    const ulonglong2* xsU = (const ulonglong2*)xs;
    float maxv = -INFINITY;

    for (int s = 0; s < 4; s++) {
        __syncthreads();
        {
            const float4* s4 = (const float4*)(xbase + (size_t)s * 32 * DDIM);
            float4* t4 = (float4*)xs;
            for (int i = tid; i < 512; i += 272) {
                int r = i >> 4, d4 = i & 15;
                t4[r * 17 + d4] = s4[i];
            }
        }
        __syncthreads();
        if (tid < 32) {
            const float4* xr = (const float4*)xs + tid * 17;
            float ssum = 0.f;
#pragma unroll
            for (int d4 = 0; d4 < 16; d4++) {
                float4 kv = xr[d4];
                ssum += kv.x * kv.x + kv.y * kv.y + kv.z * kv.z + kv.w * kv.w;
            }
            gdiag[s * 32 + tid] = DIAGC * ssum;
        }
        unsigned long long acc[2][4];
#pragma unroll
        for (int j = 0; j < 2; j++)
#pragma unroll
            for (int i = 0; i < 4; i++) acc[j][i] = 0ULL;
#pragma unroll
        for (int d4 = 0; d4 < 16; d4++) {
            ulonglong2 pa0 = psU[(ml0 + 0)  * 17 + d4];
            ulonglong2 pa1 = psU[(ml0 + 17) * 17 + d4];
            ulonglong2 pa2 = psU[(ml0 + 34) * 17 + d4];
            ulonglong2 pa3 = psU[(ml0 + 51) * 17 + d4];
#pragma unroll
            for (int j = 0; j < 2; j++) {
                ulonglong2 xa = xsU[(rg * 2 + j) * 17 + d4];
                FMA2(acc[j][0], xa.x, pa0.x); FMA2(acc[j][0], xa.y, pa0.y);
                FMA2(acc[j][1], xa.x, pa1.x); FMA2(acc[j][1], xa.y, pa1.y);
                FMA2(acc[j][2], xa.x, pa2.x); FMA2(acc[j][2], xa.y, pa2.y);
                FMA2(acc[j][3], xa.x, pa3.x); FMA2(acc[j][3], xa.y, pa3.y);
            }
        }
#pragma unroll
        for (int j = 0; j < 2; j++) {
            int row = rg * 2 + j;
            float* drow = dbase + (size_t)(s * 32 + row) * MPAD + mbase;
#pragma unroll
            for (int i = 0; i < 4; i++) {
                float dv = NORMALIZER * pairsum(acc[j][i]);
                drow[ml0 + 17 * i] = dv;
                if (mbase + ml0 + 17 * i < MDIM) maxv = fmaxf(maxv, dv);
            }
        }
    }
    if (isK) {
        __syncthreads();
        atomicMax(&red, fenc(maxv));
        __syncthreads();
        if (tid == 0) atomicMax(&g_stab_bits, red);
    }
}

// =======================================================================
// context: kp = c1*(exp(kdash-diag-stab)+eps) for one 68-m stripe;
// REGISTER-resident Cl tile per thread (4m x 4e), FMA2 over e-pairs.
// grid (8 rowchunk, 4 stripe, 32 bh), 320 threads (289 active in GEMM).
// =======================================================================
__global__ void __launch_bounds__(320, 3) context_kernel(const float* __restrict__ vv) {
    extern __shared__ float sm[];
    float* kp = sm;                      // [32][68]
    float* vs = kp + 32 * 68;            // [32][68]
    __shared__ float diag_s[32];
    int tid = threadIdx.x;
    int bh = blockIdx.z;
    int mbase = blockIdx.y * MSTRIPE;
    int row0b = blockIdx.x * 512;

    const float* dbase = g_kdash + ((size_t)bh * NSEQ + row0b) * MPAD;
    const float* diagb = g_kdiag + bh * NSEQ + row0b;
    const float* vbase = vv + ((size_t)bh * NSEQ + row0b) * DDIM;
    const float stab = fdec(*(volatile unsigned int*)&g_stab_bits);
    const float c1 = RATIO / (float)NSEQ;

    const float4* kp4 = (const float4*)kp;
    const ulonglong2* vsU = (const ulonglong2*)vs;
    int mg = tid / 17, eg = tid % 17;    // tile (4m x 4e); active if tid < 289

    unsigned long long a[4][2];
#pragma unroll
    for (int j = 0; j < 4; j++) { a[j][0] = 0ULL; a[j][1] = 0ULL; }

    for (int s = 0; s < 16; s++) {
        __syncthreads();
        {   // V tile + ones column
            const float4* s4 = (const float4*)(vbase + (size_t)s * 32 * DDIM);
            float4* t4 = (float4*)vs;
            for (int t = tid; t < 544; t += 320) {
                int r = t / 17, e4 = t % 17;
                t4[r * 17 + e4] = (e4 < 16) ? s4[r * 16 + e4]
                                            : make_float4(1.f, 0.f, 0.f, 0.f);
            }
        }
        if (tid < 32) diag_s[tid] = diagb[s * 32 + tid] + stab;
        __syncthreads();
        {   // kp stripe with exp
            for (int t = tid; t < 544; t += 320) {
                int r = t / 17, m4 = t % 17;
                const float* drow = dbase + (size_t)(s * 32 + r) * MPAD + mbase;
                float4 dd = *(const float4*)(drow + m4 * 4);
                float dg = diag_s[r];
                int m = mbase + m4 * 4;
                float4 o;
                o.x = (m + 0 < MDIM) ? c1 * (__expf(dd.x - dg) + KEPS) : 0.f;
                o.y = (m + 1 < MDIM) ? c1 * (__expf(dd.y - dg) + KEPS) : 0.f;
                o.z = (m + 2 < MDIM) ? c1 * (__expf(dd.z - dg) + KEPS) : 0.f;
                o.w = (m + 3 < MDIM) ? c1 * (__expf(dd.w - dg) + KEPS) : 0.f;
                ((float4*)kp)[r * 17 + m4] = o;
            }
        }
        __syncthreads();
        if (tid < 289) {
#pragma unroll 4
            for (int r = 0; r < 32; r++) {
                float4 kq = kp4[r * 17 + mg];
                ulonglong2 vq = vsU[r * 17 + eg];
                unsigned long long kx = dupf(kq.x), ky = dupf(kq.y);
                unsigned long long kz = dupf(kq.z), kw = dupf(kq.w);
                FMA2(a[0][0], kx, vq.x); FMA2(a[0][1], kx, vq.y);
                FMA2(a[1][0], ky, vq.x); FMA2(a[1][1], ky, vq.y);
                FMA2(a[2][0], kz, vq.x); FMA2(a[2][1], kz, vq.y);
                FMA2(a[3][0], kw, vq.x); FMA2(a[3][1], kw, vq.y);
            }
        }
    }
    if (tid < 289) {
        float* gCT = g_CT + (size_t)bh * EROWS * MPAD;
#pragma unroll
        for (int j = 0; j < 4; j++) {
            int m = mbase + mg * 4 + j;
#pragma unroll
            for (int p = 0; p < 2; p++) {
                float lo, hi;
                unpack2(a[j][p], lo, hi);
                int e = eg * 4 + p * 2;
                atomicAdd(&gCT[(size_t)e * MPAD + m], lo);
                atomicAdd(&gCT[(size_t)(e + 1) * MPAD + m], hi);
            }
        }
    }
}

// =======================================================================
// out: qp = exp-transform(qdash, per-row stab); out = D_inv * qp @ C.
// Full 64-e per block, 2 e per lane; CsT loaded coalesced from g_CT.
// grid (32 rowchunk, 32 bh), 256 threads, 2 blocks/SM.
// =======================================================================
__global__ void __launch_bounds__(256, 2) out_kernel(float* __restrict__ out) {
    extern __shared__ float sm[];
    float* CsT    = sm;                       // [65][276]: e-rows 0..63 + den row 64
    float* qp     = CsT + 65 * CTSTR;         // [32][272]
    float* stab_s = qp + 32 * MPAD;           // 32
    float* den    = stab_s + 32;              // 32
    int tid = threadIdx.x;
    int bh = blockIdx.y;
    int row0b = blockIdx.x * 128;

    {   // coalesced CsT load from transposed g_CT; zero the 1-f4 row pad
        const float4* gCT4 = (const float4*)(g_CT + (size_t)bh * EROWS * MPAD);
        float4* CsT4 = (float4*)CsT;
        for (int i = tid; i < 65 * 68; i += 256) {
            int el = i / 68, m4 = i % 68;
            CsT4[el * 69 + m4] = gCT4[el * 68 + m4];
        }
        for (int i = tid; i < 65; i += 256)
            CsT4[i * 69 + 68] = make_float4(0.f, 0.f, 0.f, 0.f);
    }
    const float* dbase = g_qdash + ((size_t)bh * NSEQ + row0b) * MPAD;
    const float* diagb = g_qdiag + bh * NSEQ + row0b;
    float* obase = out + ((size_t)bh * NSEQ + row0b) * DDIM;

    const ulonglong2* CsU2 = (const ulonglong2*)CsT;  // row stride 69
    const ulonglong2* qpU2 = (const ulonglong2*)qp;   // row stride 68
    int lane = tid & 31, w = tid >> 5;
    int r0 = w * 4;

    for (int s = 0; s < 4; s++) {
        __syncthreads();
        {   // raw qdash -> qp
            float4* qp4 = (float4*)qp;
            for (int t = tid; t < 2176; t += 256) {
                int r = t / 68, m4 = t % 68;
                qp4[r * 68 + m4] = *(const float4*)(dbase + (size_t)(s * 32 + r) * MPAD + m4 * 4);
            }
        }
        __syncthreads();
        {   // per-row max over valid m
            int r = tid >> 3, part = tid & 7;
            float mv = -INFINITY;
            for (int m = part; m < MDIM; m += 8) mv = fmaxf(mv, qp[r * MPAD + m]);
            mv = fmaxf(mv, __shfl_xor_sync(0xffffffffu, mv, 1));
            mv = fmaxf(mv, __shfl_xor_sync(0xffffffffu, mv, 2));
            mv = fmaxf(mv, __shfl_xor_sync(0xffffffffu, mv, 4));
            if (part == 0) stab_s[r] = mv;
        }
        __syncthreads();
        {   // exp transform (pads -> 0)
            int r = tid >> 3, part = tid & 7;
            float dg = diagb[s * 32 + r] + stab_s[r];
            for (int m = part; m < MPAD; m += 8) {
                float val = 0.f;
                if (m < MDIM) val = RATIO * (__expf(qp[r * MPAD + m] - dg) + KEPS);
                qp[r * MPAD + m] = val;
            }
        }
        __syncthreads();
        {   // denominator: qp row . CsT row 64
            int r = tid >> 3, part = tid & 7;
            const float* dc = CsT + 64 * CTSTR;
            float dd = 0.f;
            for (int m = part; m < MPAD; m += 8) dd += qp[r * MPAD + m] * dc[m];
            dd += __shfl_xor_sync(0xffffffffu, dd, 1);
            dd += __shfl_xor_sync(0xffffffffu, dd, 2);
            dd += __shfl_xor_sync(0xffffffffu, dd, 4);
            if (part == 0) den[r] = dd;
        }
        __syncthreads();
        {   // GEMM: warp = 4 rows, lane = e and e+32; f32x2 over m
            unsigned long long a[4][2];
#pragma unroll
            for (int j = 0; j < 4; j++) { a[j][0] = 0ULL; a[j][1] = 0ULL; }
            const ulonglong2* c0 = CsU2 + (size_t)lane * 69;
            const ulonglong2* c1 = CsU2 + (size_t)(lane + 32) * 69;
            const ulonglong2* q0 = qpU2 + (size_t)r0 * 68;
#pragma unroll 2
            for (int qd = 0; qd < 68; qd++) {
                ulonglong2 cA = c0[qd];
                ulonglong2 cB = c1[qd];
#pragma unroll
                for (int j = 0; j < 4; j++) {
                    ulonglong2 qv = q0[j * 68 + qd];
                    FMA2(a[j][0], qv.x, cA.x); FMA2(a[j][0], qv.y, cA.y);
                    FMA2(a[j][1], qv.x, cB.x); FMA2(a[j][1], qv.y, cB.y);
                }
            }
#pragma unroll
            for (int j = 0; j < 4; j++) {
                int r = r0 + j;
                float di = 1.0f / den[r];
                float* orow = obase + (size_t)(s * 32 + r) * DDIM;
                orow[lane]      = pairsum(a[j][0]) * di;
                orow[lane + 32] = pairsum(a[j][1]) * di;
            }
        }
    }
}

// =======================================================================
extern "C" void kernel_launch(void* const* d_in, const int* in_sizes, int n_in,
                              void* d_out, int out_size) {
    int pidx = -1;
    for (int i = 0; i < n_in; i++) if (in_sizes[i] == MDIM * DDIM) pidx = i;
    const float* rest[3] = {nullptr, nullptr, nullptr};
    int rc = 0;
    for (int i = 0; i < n_in && rc < 3; i++) {
        if (i == pidx) continue;
        rest[rc++] = (const float*)d_in[i];
    }
    const float* q = rest[0];
    const float* k = rest[1];
    const float* v = rest[2];
    const float* proj = (const float*)d_in[pidx];
    float* out = (float*)d_out;

    int smA = (MSTRIPE * 68 + 32 * 68) * (int)sizeof(float);               // ~27 KB
    int smB = (32 * 68 + 32 * 68) * (int)sizeof(float);                    // ~17 KB
    int smC = (65 * CTSTR + 32 * MPAD + 64) * (int)sizeof(float);          // ~107 KB

    cudaFuncSetAttribute(dash_kernel,    cudaFuncAttributeMaxDynamicSharedMemorySize, smA);
    cudaFuncSetAttribute(context_kernel, cudaFuncAttributeMaxDynamicSharedMemorySize, smB);
    cudaFuncSetAttribute(out_kernel,     cudaFuncAttributeMaxDynamicSharedMemorySize, smC);

    init_kernel<<<512, 256>>>();
    dash_kernel<<<dim3(32, 4, 32), 272, smA>>>(k, proj, 1);
    dash_kernel<<<dim3(32, 4, 32), 272, smA>>>(q, proj, 0);
    context_kernel<<<dim3(8, 4, 32), 320, smB>>>(v);
    out_kernel<<<dim3(32, 32), 256, smC>>>(out);
}

// round 8
// speedup vs baseline: 2.0735x; 1.5374x over previous
#include <cuda_runtime.h>
#include <cuda_bf16.h>
#include <math.h>

#define BH 32
#define NSEQ 4096
#define DDIM 64
#define MDIM 266
#define MPAD 272            // dash row stride (floats)
#define MSTRIPE 68
#define ECOLS 65
#define EROWS 68
#define CTSTR 276
#define NPAD 288            // mma n-dim padding (36 blocks of 8)
#define BROW 144            // bf16 smem row stride in BYTES (9x16B -> conflict-free)
#define NORMALIZER 0.3535533905932738f   // 64^-0.25
#define DIAGC 0.0625f                    // 0.5 * 64^-0.5
#define KEPS 1e-4f
#define RATIO 0.06131393835f             // 266^-0.5

// ---------------- f32x2 helpers (CUDA-core kernels) ----------------------
#define FMA2(acc, a, b) asm("fma.rn.f32x2 %0, %1, %2, %0;" : "+l"(acc) : "l"(a), "l"(b))
__device__ __forceinline__ float pairsum(unsigned long long v) {
    float lo, hi;
    asm("mov.b64 {%0,%1}, %2;" : "=f"(lo), "=f"(hi) : "l"(v));
    return lo + hi;
}
__device__ __forceinline__ void unpack2(unsigned long long v, float& lo, float& hi) {
    asm("mov.b64 {%0,%1}, %2;" : "=f"(lo), "=f"(hi) : "l"(v));
}
__device__ __forceinline__ unsigned long long dupf(float x) {
    unsigned long long r;
    asm("mov.b64 %0, {%1,%1};" : "=l"(r) : "f"(x));
    return r;
}

// ---------------- warp-mma helpers (baseline sm_80 features) --------------
__device__ __forceinline__ unsigned int smem_u32(const void* p) {
    unsigned int a;
    asm("{ .reg .u64 t; cvta.to.shared.u64 t, %1; cvt.u32.u64 %0, t; }" : "=r"(a) : "l"(p));
    return a;
}
#define LDM_X4(d, addr) \
    asm volatile("ldmatrix.sync.aligned.m8n8.x4.shared.b16 {%0,%1,%2,%3}, [%4];" \
        : "=r"((d)[0]), "=r"((d)[1]), "=r"((d)[2]), "=r"((d)[3]) : "r"(addr))
#define LDM_X2(d0, d1, addr) \
    asm volatile("ldmatrix.sync.aligned.m8n8.x2.shared.b16 {%0,%1}, [%2];" \
        : "=r"(d0), "=r"(d1) : "r"(addr))
#define MMA_BF16(c, a, b0, b1) \
    asm volatile("mma.sync.aligned.m16n8k16.row.col.f32.bf16.bf16.f32 " \
        "{%0,%1,%2,%3}, {%4,%5,%6,%7}, {%8,%9}, {%0,%1,%2,%3};" \
        : "+f"((c)[0]), "+f"((c)[1]), "+f"((c)[2]), "+f"((c)[3]) \
        : "r"((a)[0]), "r"((a)[1]), "r"((a)[2]), "r"((a)[3]), "r"(b0), "r"(b1))

__device__ __forceinline__ void split2(float x, float y, unsigned int& hi, unsigned int& lo) {
    __nv_bfloat16 hx = __float2bfloat16(x);
    __nv_bfloat16 hy = __float2bfloat16(y);
    float rx = x - __bfloat162float(hx);
    float ry = y - __bfloat162float(hy);
    hi = ((unsigned)__bfloat16_as_ushort(hy) << 16) | (unsigned)__bfloat16_as_ushort(hx);
    lo = ((unsigned)__bfloat16_as_ushort(__float2bfloat16(ry)) << 16)
       | (unsigned)__bfloat16_as_ushort(__float2bfloat16(rx));
}

// ---------------- scratch (static device globals; no allocation) ----------
__device__ unsigned int g_stab_bits;
__device__ float g_CT[(size_t)BH * EROWS * MPAD];        // [bh][e][m]
__device__ float g_kdash[(size_t)BH * NSEQ * MPAD];
__device__ float g_qdash[(size_t)BH * NSEQ * MPAD];
__device__ float g_kdiag[BH * NSEQ];
__device__ float g_qdiag[BH * NSEQ];

__device__ __forceinline__ unsigned int fenc(float f) {
    unsigned int b = __float_as_uint(f);
    return (b & 0x80000000u) ? ~b : (b | 0x80000000u);
}
__device__ __forceinline__ float fdec(unsigned int u) {
    return (u & 0x80000000u) ? __uint_as_float(u & 0x7FFFFFFFu) : __uint_as_float(~u);
}

__global__ void init_kernel() {
    int i = blockIdx.x * blockDim.x + threadIdx.x;
    if (i == 0) g_stab_bits = 0u;
    int stride = gridDim.x * blockDim.x;
    for (size_t idx = i; idx < (size_t)BH * EROWS * MPAD; idx += stride) g_CT[idx] = 0.0f;
}

// =======================================================================
// dash_mma: dash = (NORMALIZER*X) @ P^T via mma.sync bf16x3 (hh+hl+lh).
// grid BH*4 (1024 rows/CTA, 8 iters of 128), 256 threads / 8 warps.
// SMEM: A_hi[128xBROW], A_lo, P_hi[288xBROW], P_lo   (~120 KB)
// Warp (rg, ng): rows rg*32..+32; n = ng*144 + pass*72 (9 n8-blocks).
// =======================================================================
#define SM_AHI 0
#define SM_ALO (128 * BROW)
#define SM_PHI (2 * 128 * BROW)
#define SM_PLO (SM_PHI + NPAD * BROW)
#define SM_DASH_TOTAL (SM_PLO + NPAD * BROW)

__global__ void __launch_bounds__(256, 1)
dash_mma_kernel(const float* __restrict__ x, const float* __restrict__ proj, int isK) {
    extern __shared__ char smc[];
    unsigned int sb = smem_u32(smc);
    __shared__ unsigned int red;
    int tid = threadIdx.x, wid = tid >> 5, lid = tid & 31;
    int g = lid >> 2, tc = lid & 3;
    int bh = blockIdx.x >> 2, chunk = blockIdx.x & 3;
    if (tid == 0) red = 0u;

    // P split -> smem once (rows >= 266 zero)
    {
        const float4* p4 = (const float4*)proj;
        for (int i = tid; i < NPAD * 16; i += 256) {
            int m = i >> 4, gg = i & 15;
            float4 v = (m < MDIM) ? p4[m * 16 + gg] : make_float4(0.f, 0.f, 0.f, 0.f);
            unsigned int h0, l0, h1, l1;
            split2(v.x, v.y, h0, l0);
            split2(v.z, v.w, h1, l1);
            *(uint2*)(smc + SM_PHI + m * BROW + gg * 8) = make_uint2(h0, h1);
            *(uint2*)(smc + SM_PLO + m * BROW + gg * 8) = make_uint2(l0, l1);
        }
    }

    const float* xbase = x + ((size_t)bh * NSEQ + chunk * 1024) * DDIM;
    float* dashp = isK ? g_kdash : g_qdash;
    float* diagp = isK ? g_kdiag : g_qdiag;
    float maxv = -INFINITY;

    // warp tiling
    int rg = wid & 3, ng = wid >> 2;
    int r0w = rg * 32;
    // ldmatrix lane address components
    int a_row = ((lid >> 3) & 1) * 8 + (lid & 7);
    int a_k8  = ((lid >> 4) & 1) * 8;
    unsigned int aHi0 = sb + SM_AHI + (unsigned)((r0w + a_row) * BROW + a_k8 * 2);
    unsigned int aLo0 = aHi0 + (SM_ALO - SM_AHI);
    int b_row = lid & 7;
    int b_k8  = ((lid >> 3) & 1) * 8;
    unsigned int bHiL = sb + SM_PHI + (unsigned)(b_row * BROW + b_k8 * 2);
    unsigned int bLoL = bHiL + (SM_PLO - SM_PHI);

    for (int s = 0; s < 8; s++) {
        __syncthreads();   // prior iter's ldmatrix done before overwriting A
        {   // X tile: thread = (row, half); coalesced f4 loads; diag + split
            int row = tid >> 1, half = tid & 1;
            const float4* xsrc = (const float4*)(xbase + (size_t)s * 128 * DDIM);
            float ssum = 0.f;
#pragma unroll
            for (int j = 0; j < 8; j++) {
                float4 v = xsrc[tid * 8 + j];
                ssum += v.x * v.x + v.y * v.y + v.z * v.z + v.w * v.w;
                unsigned int h0, l0, h1, l1;
                split2(v.x * NORMALIZER, v.y * NORMALIZER, h0, l0);
                split2(v.z * NORMALIZER, v.w * NORMALIZER, h1, l1);
                int gg = half * 8 + j;
                *(uint2*)(smc + SM_AHI + row * BROW + gg * 8) = make_uint2(h0, h1);
                *(uint2*)(smc + SM_ALO + row * BROW + gg * 8) = make_uint2(l0, l1);
            }
            ssum += __shfl_xor_sync(0xffffffffu, ssum, 1);
            if (!half) diagp[(size_t)bh * NSEQ + chunk * 1024 + s * 128 + row] = DIAGC * ssum;
        }
        __syncthreads();

        float* dbase = dashp + ((size_t)bh * NSEQ + chunk * 1024 + s * 128) * MPAD;
#pragma unroll
        for (int p = 0; p < 2; p++) {
            int n0w = ng * 144 + p * 72;
            unsigned int bHiP = bHiL + (unsigned)(n0w * BROW);
            unsigned int bLoP = bLoL + (unsigned)(n0w * BROW);
            float c[2][9][4];
#pragma unroll
            for (int rb = 0; rb < 2; rb++)
#pragma unroll
                for (int nb = 0; nb < 9; nb++)
#pragma unroll
                    for (int q = 0; q < 4; q++) c[rb][nb][q] = 0.f;

#pragma unroll
            for (int kk = 0; kk < 4; kk++) {
                unsigned int ah[2][4], al[2][4];
                LDM_X4(ah[0], aHi0 + kk * 32);
                LDM_X4(ah[1], aHi0 + 16 * BROW + kk * 32);
                LDM_X4(al[0], aLo0 + kk * 32);
                LDM_X4(al[1], aLo0 + 16 * BROW + kk * 32);
#pragma unroll
                for (int nb = 0; nb < 9; nb++) {
                    unsigned int bh0, bh1, bl0, bl1;
                    LDM_X2(bh0, bh1, bHiP + nb * 8 * BROW + kk * 32);
                    LDM_X2(bl0, bl1, bLoP + nb * 8 * BROW + kk * 32);
#pragma unroll
                    for (int rb = 0; rb < 2; rb++) {
                        MMA_BF16(c[rb][nb], ah[rb], bh0, bh1);
                        MMA_BF16(c[rb][nb], ah[rb], bl0, bl1);
                        MMA_BF16(c[rb][nb], al[rb], bh0, bh1);
                    }
                }
            }
            // epilogue: write float2 pairs; track k-max over valid n
#pragma unroll
            for (int rb = 0; rb < 2; rb++) {
                int rA = r0w + rb * 16 + g;
#pragma unroll
                for (int nb = 0; nb < 9; nb++) {
                    int n = n0w + nb * 8 + tc * 2;
                    if (n < MPAD) {
                        *(float2*)(dbase + (size_t)rA * MPAD + n) =
                            make_float2(c[rb][nb][0], c[rb][nb][1]);
                        *(float2*)(dbase + (size_t)(rA + 8) * MPAD + n) =
                            make_float2(c[rb][nb][2], c[rb][nb][3]);
                    }
                    if (isK) {
                        if (n < MDIM) maxv = fmaxf(maxv, fmaxf(c[rb][nb][0], c[rb][nb][2]));
                        if (n + 1 < MDIM) maxv = fmaxf(maxv, fmaxf(c[rb][nb][1], c[rb][nb][3]));
                    }
                }
            }
        }
    }

    if (isK) {
#pragma unroll
        for (int o = 16; o; o >>= 1) maxv = fmaxf(maxv, __shfl_xor_sync(0xffffffffu, maxv, o));
        if (lid == 0) atomicMax(&red, fenc(maxv));
        __syncthreads();
        if (tid == 0) atomicMax(&g_stab_bits, red);
    }
}

// =======================================================================
// context: kp = c1*(exp(kdash-diag-stab)+eps); register Cl tile 4m x 4e.
// grid (8 rowchunk, 4 stripe, 32 bh), 320 threads. (unchanged, R6-passing)
// =======================================================================
__global__ void __launch_bounds__(320, 3) context_kernel(const float* __restrict__ vv) {
    extern __shared__ float sm[];
    float* kp = sm;                      // [32][68]
    float* vs = kp + 32 * 68;            // [32][68]
    __shared__ float diag_s[32];
    int tid = threadIdx.x;
    int bh = blockIdx.z;
    int mbase = blockIdx.y * MSTRIPE;
    int row0b = blockIdx.x * 512;

    const float* dbase = g_kdash + ((size_t)bh * NSEQ + row0b) * MPAD;
    const float* diagb = g_kdiag + bh * NSEQ + row0b;
    const float* vbase = vv + ((size_t)bh * NSEQ + row0b) * DDIM;
    const float stab = fdec(*(volatile unsigned int*)&g_stab_bits);
    const float c1 = RATIO / (float)NSEQ;

    const float4* kp4 = (const float4*)kp;
    const ulonglong2* vsU = (const ulonglong2*)vs;
    int mg = tid / 17, eg = tid % 17;

    unsigned long long a[4][2];
#pragma unroll
    for (int j = 0; j < 4; j++) { a[j][0] = 0ULL; a[j][1] = 0ULL; }

    for (int s = 0; s < 16; s++) {
        __syncthreads();
        {
            const float4* s4 = (const float4*)(vbase + (size_t)s * 32 * DDIM);
            float4* t4 = (float4*)vs;
            for (int t = tid; t < 544; t += 320) {
                int r = t / 17, e4 = t % 17;
                t4[r * 17 + e4] = (e4 < 16) ? s4[r * 16 + e4]
                                            : make_float4(1.f, 0.f, 0.f, 0.f);
            }
        }
        if (tid < 32) diag_s[tid] = diagb[s * 32 + tid] + stab;
        __syncthreads();
        {
            for (int t = tid; t < 544; t += 320) {
                int r = t / 17, m4 = t % 17;
                const float* drow = dbase + (size_t)(s * 32 + r) * MPAD + mbase;
                float4 dd = *(const float4*)(drow + m4 * 4);
                float dg = diag_s[r];
                int m = mbase + m4 * 4;
                float4 o;
                o.x = (m + 0 < MDIM) ? c1 * (__expf(dd.x - dg) + KEPS) : 0.f;
                o.y = (m + 1 < MDIM) ? c1 * (__expf(dd.y - dg) + KEPS) : 0.f;
                o.z = (m + 2 < MDIM) ? c1 * (__expf(dd.z - dg) + KEPS) : 0.f;
                o.w = (m + 3 < MDIM) ? c1 * (__expf(dd.w - dg) + KEPS) : 0.f;
                ((float4*)kp)[r * 17 + m4] = o;
            }
        }
        __syncthreads();
        if (tid < 289) {
#pragma unroll 4
            for (int r = 0; r < 32; r++) {
                float4 kq = kp4[r * 17 + mg];
                ulonglong2 vq = vsU[r * 17 + eg];
                unsigned long long kx = dupf(kq.x), ky = dupf(kq.y);
                unsigned long long kz = dupf(kq.z), kw = dupf(kq.w);
                FMA2(a[0][0], kx, vq.x); FMA2(a[0][1], kx, vq.y);
                FMA2(a[1][0], ky, vq.x); FMA2(a[1][1], ky, vq.y);
                FMA2(a[2][0], kz, vq.x); FMA2(a[2][1], kz, vq.y);
                FMA2(a[3][0], kw, vq.x); FMA2(a[3][1], kw, vq.y);
            }
        }
    }
    if (tid < 289) {
        float* gCT = g_CT + (size_t)bh * EROWS * MPAD;
#pragma unroll
        for (int j = 0; j < 4; j++) {
            int m = mbase + mg * 4 + j;
#pragma unroll
            for (int p = 0; p < 2; p++) {
                float lo, hi;
                unpack2(a[j][p], lo, hi);
                int e = eg * 4 + p * 2;
                atomicAdd(&gCT[(size_t)e * MPAD + m], lo);
                atomicAdd(&gCT[(size_t)(e + 1) * MPAD + m], hi);
            }
        }
    }
}

// =======================================================================
// out: qp exp-transform + out = D_inv * qp @ C. (unchanged, R6-passing)
// grid (32 rowchunk, 32 bh), 256 threads.
// =======================================================================
__global__ void __launch_bounds__(256, 2) out_kernel(float* __restrict__ out) {
    extern __shared__ float sm[];
    float* CsT    = sm;                       // [65][276]
    float* qp     = CsT + 65 * CTSTR;         // [32][272]
    float* stab_s = qp + 32 * MPAD;
    float* den    = stab_s + 32;
    int tid = threadIdx.x;
    int bh = blockIdx.y;
    int row0b = blockIdx.x * 128;

    {
        const float4* gCT4 = (const float4*)(g_CT + (size_t)bh * EROWS * MPAD);
        float4* CsT4 = (float4*)CsT;
        for (int i = tid; i < 65 * 68; i += 256) {
            int el = i / 68, m4 = i % 68;
            CsT4[el * 69 + m4] = gCT4[el * 68 + m4];
        }
        for (int i = tid; i < 65; i += 256)
            CsT4[i * 69 + 68] = make_float4(0.f, 0.f, 0.f, 0.f);
    }
    const float* dbase = g_qdash + ((size_t)bh * NSEQ + row0b) * MPAD;
    const float* diagb = g_qdiag + bh * NSEQ + row0b;
    float* obase = out + ((size_t)bh * NSEQ + row0b) * DDIM;

    const ulonglong2* CsU2 = (const ulonglong2*)CsT;
    const ulonglong2* qpU2 = (const ulonglong2*)qp;
    int lane = tid & 31, w = tid >> 5;
    int r0 = w * 4;

    for (int s = 0; s < 4; s++) {
        __syncthreads();
        {
            float4* qp4 = (float4*)qp;
            for (int t = tid; t < 2176; t += 256) {
                int r = t / 68, m4 = t % 68;
                qp4[r * 68 + m4] = *(const float4*)(dbase + (size_t)(s * 32 + r) * MPAD + m4 * 4);
            }
        }
        __syncthreads();
        {
            int r = tid >> 3, part = tid & 7;
            float mv = -INFINITY;
            for (int m = part; m < MDIM; m += 8) mv = fmaxf(mv, qp[r * MPAD + m]);
            mv = fmaxf(mv, __shfl_xor_sync(0xffffffffu, mv, 1));
            mv = fmaxf(mv, __shfl_xor_sync(0xffffffffu, mv, 2));
            mv = fmaxf(mv, __shfl_xor_sync(0xffffffffu, mv, 4));
            if (part == 0) stab_s[r] = mv;
        }
        __syncthreads();
        {
            int r = tid >> 3, part = tid & 7;
            float dg = diagb[s * 32 + r] + stab_s[r];
            for (int m = part; m < MPAD; m += 8) {
                float val = 0.f;
                if (m < MDIM) val = RATIO * (__expf(qp[r * MPAD + m] - dg) + KEPS);
                qp[r * MPAD + m] = val;
            }
        }
        __syncthreads();
        {
            int r = tid >> 3, part = tid & 7;
            const float* dc = CsT + 64 * CTSTR;
            float dd = 0.f;
            for (int m = part; m < MPAD; m += 8) dd += qp[r * MPAD + m] * dc[m];
            dd += __shfl_xor_sync(0xffffffffu, dd, 1);
            dd += __shfl_xor_sync(0xffffffffu, dd, 2);
            dd += __shfl_xor_sync(0xffffffffu, dd, 4);
            if (part == 0) den[r] = dd;
        }
        __syncthreads();
        {
            unsigned long long a[4][2];
#pragma unroll
            for (int j = 0; j < 4; j++) { a[j][0] = 0ULL; a[j][1] = 0ULL; }
            const ulonglong2* c0 = CsU2 + (size_t)lane * 69;
            const ulonglong2* c1 = CsU2 + (size_t)(lane + 32) * 69;
            const ulonglong2* q0 = qpU2 + (size_t)r0 * 68;
#pragma unroll 2
            for (int qd = 0; qd < 68; qd++) {
                ulonglong2 cA = c0[qd];
                ulonglong2 cB = c1[qd];
#pragma unroll
                for (int j = 0; j < 4; j++) {
                    ulonglong2 qv = q0[j * 68 + qd];
                    FMA2(a[j][0], qv.x, cA.x); FMA2(a[j][0], qv.y, cA.y);
                    FMA2(a[j][1], qv.x, cB.x); FMA2(a[j][1], qv.y, cB.y);
                }
            }
#pragma unroll
            for (int j = 0; j < 4; j++) {
                int r = r0 + j;
                float di = 1.0f / den[r];
                float* orow = obase + (size_t)(s * 32 + r) * DDIM;
                orow[lane]      = pairsum(a[j][0]) * di;
                orow[lane + 32] = pairsum(a[j][1]) * di;
            }
        }
    }
}

// =======================================================================
extern "C" void kernel_launch(void* const* d_in, const int* in_sizes, int n_in,
                              void* d_out, int out_size) {
    int pidx = -1;
    for (int i = 0; i < n_in; i++) if (in_sizes[i] == MDIM * DDIM) pidx = i;
    const float* rest[3] = {nullptr, nullptr, nullptr};
    int rc = 0;
    for (int i = 0; i < n_in && rc < 3; i++) {
        if (i == pidx) continue;
        rest[rc++] = (const float*)d_in[i];
    }
    const float* q = rest[0];
    const float* k = rest[1];
    const float* v = rest[2];
    const float* proj = (const float*)d_in[pidx];
    float* out = (float*)d_out;

    int smB = (32 * 68 + 32 * 68) * (int)sizeof(float);                    // ~17 KB
    int smC = (65 * CTSTR + 32 * MPAD + 64) * (int)sizeof(float);          // ~107 KB

    cudaFuncSetAttribute(dash_mma_kernel, cudaFuncAttributeMaxDynamicSharedMemorySize, SM_DASH_TOTAL);
    cudaFuncSetAttribute(context_kernel,  cudaFuncAttributeMaxDynamicSharedMemorySize, smB);
    cudaFuncSetAttribute(out_kernel,      cudaFuncAttributeMaxDynamicSharedMemorySize, smC);

    init_kernel<<<512, 256>>>();
    dash_mma_kernel<<<BH * 4, 256, SM_DASH_TOTAL>>>(k, proj, 1);
    dash_mma_kernel<<<BH * 4, 256, SM_DASH_TOTAL>>>(q, proj, 0);
    context_kernel<<<dim3(8, 4, 32), 320, smB>>>(v);
    out_kernel<<<dim3(32, 32), 256, smC>>>(out);
}

// round 9
// speedup vs baseline: 2.1012x; 1.0134x over previous
#include <cuda_runtime.h>
#include <cuda_bf16.h>
#include <math.h>

#define BH 32
#define NSEQ 4096
#define DDIM 64
#define MDIM 266
#define MPAD 272            // dash row stride (floats)
#define ECOLS 65
#define EROWS 68
#define CTSTR 276
#define NPAD 288            // dash mma n-dim padding
#define BROW 144            // dash bf16 smem row stride BYTES
#define NORMALIZER 0.3535533905932738f   // 64^-0.25
#define DIAGC 0.0625f                    // 0.5 * 64^-0.5
#define KEPS 1e-4f
#define RATIO 0.06131393835f             // 266^-0.5

// ---------------- f32x2 helpers ----------------
#define FMA2(acc, a, b) asm("fma.rn.f32x2 %0, %1, %2, %0;" : "+l"(acc) : "l"(a), "l"(b))
__device__ __forceinline__ float pairsum(unsigned long long v) {
    float lo, hi;
    asm("mov.b64 {%0,%1}, %2;" : "=f"(lo), "=f"(hi) : "l"(v));
    return lo + hi;
}

// ---------------- warp-mma helpers (non-'a' features) --------------
__device__ __forceinline__ unsigned int smem_u32(const void* p) {
    unsigned int a;
    asm("{ .reg .u64 t; cvta.to.shared.u64 t, %1; cvt.u32.u64 %0, t; }" : "=r"(a) : "l"(p));
    return a;
}
#define LDM_X4(d, addr) \
    asm volatile("ldmatrix.sync.aligned.m8n8.x4.shared.b16 {%0,%1,%2,%3}, [%4];" \
        : "=r"((d)[0]), "=r"((d)[1]), "=r"((d)[2]), "=r"((d)[3]) : "r"(addr))
#define LDM_X2(d0, d1, addr) \
    asm volatile("ldmatrix.sync.aligned.m8n8.x2.shared.b16 {%0,%1}, [%2];" \
        : "=r"(d0), "=r"(d1) : "r"(addr))
#define LDM_X4T(d, addr) \
    asm volatile("ldmatrix.sync.aligned.m8n8.x4.trans.shared.b16 {%0,%1,%2,%3}, [%4];" \
        : "=r"((d)[0]), "=r"((d)[1]), "=r"((d)[2]), "=r"((d)[3]) : "r"(addr))
#define LDM_X2T(d0, d1, addr) \
    asm volatile("ldmatrix.sync.aligned.m8n8.x2.trans.shared.b16 {%0,%1}, [%2];" \
        : "=r"(d0), "=r"(d1) : "r"(addr))
#define MMA_BF16(c, a, b0, b1) \
    asm volatile("mma.sync.aligned.m16n8k16.row.col.f32.bf16.bf16.f32 " \
        "{%0,%1,%2,%3}, {%4,%5,%6,%7}, {%8,%9}, {%0,%1,%2,%3};" \
        : "+f"((c)[0]), "+f"((c)[1]), "+f"((c)[2]), "+f"((c)[3]) \
        : "r"((a)[0]), "r"((a)[1]), "r"((a)[2]), "r"((a)[3]), "r"(b0), "r"(b1))

__device__ __forceinline__ void split2(float x, float y, unsigned int& hi, unsigned int& lo) {
    __nv_bfloat16 hx = __float2bfloat16(x);
    __nv_bfloat16 hy = __float2bfloat16(y);
    float rx = x - __bfloat162float(hx);
    float ry = y - __bfloat162float(hy);
    hi = ((unsigned)__bfloat16_as_ushort(hy) << 16) | (unsigned)__bfloat16_as_ushort(hx);
    lo = ((unsigned)__bfloat16_as_ushort(__float2bfloat16(ry)) << 16)
       | (unsigned)__bfloat16_as_ushort(__float2bfloat16(rx));
}

// ---------------- scratch ----------------
__device__ unsigned int g_stab_bits;
__device__ float g_CT[(size_t)BH * EROWS * MPAD];        // [bh][e][m]
__device__ float g_kdash[(size_t)BH * NSEQ * MPAD];
__device__ float g_qdash[(size_t)BH * NSEQ * MPAD];
__device__ float g_kdiag[BH * NSEQ];
__device__ float g_qdiag[BH * NSEQ];

__device__ __forceinline__ unsigned int fenc(float f) {
    unsigned int b = __float_as_uint(f);
    return (b & 0x80000000u) ? ~b : (b | 0x80000000u);
}
__device__ __forceinline__ float fdec(unsigned int u) {
    return (u & 0x80000000u) ? __uint_as_float(u & 0x7FFFFFFFu) : __uint_as_float(~u);
}

__global__ void init_kernel() {
    int i = blockIdx.x * blockDim.x + threadIdx.x;
    if (i == 0) g_stab_bits = 0u;
    int stride = gridDim.x * blockDim.x;
    for (size_t idx = i; idx < (size_t)BH * EROWS * MPAD; idx += stride) g_CT[idx] = 0.0f;
}

// =======================================================================
// dash_mma (unchanged from R8-passing): dash = (NORM*X)@P^T, bf16x3 mma.
// =======================================================================
#define SM_AHI 0
#define SM_ALO (128 * BROW)
#define SM_PHI (2 * 128 * BROW)
#define SM_PLO (SM_PHI + NPAD * BROW)
#define SM_DASH_TOTAL (SM_PLO + NPAD * BROW)

__global__ void __launch_bounds__(256, 1)
dash_mma_kernel(const float* __restrict__ x, const float* __restrict__ proj, int isK) {
    extern __shared__ char smc[];
    unsigned int sb = smem_u32(smc);
    __shared__ unsigned int red;
    int tid = threadIdx.x, wid = tid >> 5, lid = tid & 31;
    int g = lid >> 2, tc = lid & 3;
    int bh = blockIdx.x >> 2, chunk = blockIdx.x & 3;
    if (tid == 0) red = 0u;

    {
        const float4* p4 = (const float4*)proj;
        for (int i = tid; i < NPAD * 16; i += 256) {
            int m = i >> 4, gg = i & 15;
            float4 v = (m < MDIM) ? p4[m * 16 + gg] : make_float4(0.f, 0.f, 0.f, 0.f);
            unsigned int h0, l0, h1, l1;
            split2(v.x, v.y, h0, l0);
            split2(v.z, v.w, h1, l1);
            *(uint2*)(smc + SM_PHI + m * BROW + gg * 8) = make_uint2(h0, h1);
            *(uint2*)(smc + SM_PLO + m * BROW + gg * 8) = make_uint2(l0, l1);
        }
    }

    const float* xbase = x + ((size_t)bh * NSEQ + chunk * 1024) * DDIM;
    float* dashp = isK ? g_kdash : g_qdash;
    float* diagp = isK ? g_kdiag : g_qdiag;
    float maxv = -INFINITY;

    int rg = wid & 3, ng = wid >> 2;
    int r0w = rg * 32;
    int a_row = ((lid >> 3) & 1) * 8 + (lid & 7);
    int a_k8  = ((lid >> 4) & 1) * 8;
    unsigned int aHi0 = sb + SM_AHI + (unsigned)((r0w + a_row) * BROW + a_k8 * 2);
    unsigned int aLo0 = aHi0 + (SM_ALO - SM_AHI);
    int b_row = lid & 7;
    int b_k8  = ((lid >> 3) & 1) * 8;
    unsigned int bHiL = sb + SM_PHI + (unsigned)(b_row * BROW + b_k8 * 2);
    unsigned int bLoL = bHiL + (SM_PLO - SM_PHI);

    for (int s = 0; s < 8; s++) {
        __syncthreads();
        {
            int row = tid >> 1, half = tid & 1;
            const float4* xsrc = (const float4*)(xbase + (size_t)s * 128 * DDIM);
            float ssum = 0.f;
#pragma unroll
            for (int j = 0; j < 8; j++) {
                float4 v = xsrc[tid * 8 + j];
                ssum += v.x * v.x + v.y * v.y + v.z * v.z + v.w * v.w;
                unsigned int h0, l0, h1, l1;
                split2(v.x * NORMALIZER, v.y * NORMALIZER, h0, l0);
                split2(v.z * NORMALIZER, v.w * NORMALIZER, h1, l1);
                int gg = half * 8 + j;
                *(uint2*)(smc + SM_AHI + row * BROW + gg * 8) = make_uint2(h0, h1);
                *(uint2*)(smc + SM_ALO + row * BROW + gg * 8) = make_uint2(l0, l1);
            }
            ssum += __shfl_xor_sync(0xffffffffu, ssum, 1);
            if (!half) diagp[(size_t)bh * NSEQ + chunk * 1024 + s * 128 + row] = DIAGC * ssum;
        }
        __syncthreads();

        float* dbase = dashp + ((size_t)bh * NSEQ + chunk * 1024 + s * 128) * MPAD;
#pragma unroll
        for (int p = 0; p < 2; p++) {
            int n0w = ng * 144 + p * 72;
            unsigned int bHiP = bHiL + (unsigned)(n0w * BROW);
            unsigned int bLoP = bLoL + (unsigned)(n0w * BROW);
            float c[2][9][4];
#pragma unroll
            for (int rb = 0; rb < 2; rb++)
#pragma unroll
                for (int nb = 0; nb < 9; nb++)
#pragma unroll
                    for (int q = 0; q < 4; q++) c[rb][nb][q] = 0.f;

#pragma unroll
            for (int kk = 0; kk < 4; kk++) {
                unsigned int ah[2][4], al[2][4];
                LDM_X4(ah[0], aHi0 + kk * 32);
                LDM_X4(ah[1], aHi0 + 16 * BROW + kk * 32);
                LDM_X4(al[0], aLo0 + kk * 32);
                LDM_X4(al[1], aLo0 + 16 * BROW + kk * 32);
#pragma unroll
                for (int nb = 0; nb < 9; nb++) {
                    unsigned int bh0, bh1, bl0, bl1;
                    LDM_X2(bh0, bh1, bHiP + nb * 8 * BROW + kk * 32);
                    LDM_X2(bl0, bl1, bLoP + nb * 8 * BROW + kk * 32);
#pragma unroll
                    for (int rb = 0; rb < 2; rb++) {
                        MMA_BF16(c[rb][nb], ah[rb], bh0, bh1);
                        MMA_BF16(c[rb][nb], ah[rb], bl0, bl1);
                        MMA_BF16(c[rb][nb], al[rb], bh0, bh1);
                    }
                }
            }
#pragma unroll
            for (int rb = 0; rb < 2; rb++) {
                int rA = r0w + rb * 16 + g;
#pragma unroll
                for (int nb = 0; nb < 9; nb++) {
                    int n = n0w + nb * 8 + tc * 2;
                    if (n < MPAD) {
                        *(float2*)(dbase + (size_t)rA * MPAD + n) =
                            make_float2(c[rb][nb][0], c[rb][nb][1]);
                        *(float2*)(dbase + (size_t)(rA + 8) * MPAD + n) =
                            make_float2(c[rb][nb][2], c[rb][nb][3]);
                    }
                    if (isK) {
                        if (n < MDIM) maxv = fmaxf(maxv, fmaxf(c[rb][nb][0], c[rb][nb][2]));
                        if (n + 1 < MDIM) maxv = fmaxf(maxv, fmaxf(c[rb][nb][1], c[rb][nb][3]));
                    }
                }
            }
        }
    }

    if (isK) {
#pragma unroll
        for (int o = 16; o; o >>= 1) maxv = fmaxf(maxv, __shfl_xor_sync(0xffffffffu, maxv, o));
        if (lid == 0) atomicMax(&red, fenc(maxv));
        __syncthreads();
        if (tid == 0) atomicMax(&g_stab_bits, red);
    }
}

// =======================================================================
// context_mma: C[m][e] = sum_r kp[r][m] * [V|1][r][e] via mma bf16x3.
// i=m (17 m16-tiles), j=e (9 n8-tiles), k=r; operands stored natural
// row-major, transposed by ldmatrix.trans. grid (4 rowchunk, 32 bh),
// 288 threads (9 warps); warp owns m-tiles {w, w+9}; 32 subtiles of 32 r.
// SMEM: kp_hi/lo [32][280]bf16 (560B rows), v_hi/lo [32][88]bf16 (176B).
// =======================================================================
#define KROWB 560
#define VROWB 176
#define SM2_KH 0
#define SM2_KL 17920
#define SM2_VH 35840
#define SM2_VL 41472
#define SM2_TOTAL 47104

__global__ void __launch_bounds__(288, 1)
context_mma_kernel(const float* __restrict__ vv) {
    extern __shared__ char smc[];
    unsigned int sb = smem_u32(smc);
    int tid = threadIdx.x, wid = tid >> 5, lid = tid & 31;
    int g = lid >> 2, tc = lid & 3;
    int bh = blockIdx.y;
    int row0b = blockIdx.x * 1024;

    const float* dbase = g_kdash + ((size_t)bh * NSEQ + row0b) * MPAD;
    const float* diagb = g_kdiag + bh * NSEQ + row0b;
    const float* vbase = vv + ((size_t)bh * NSEQ + row0b) * DDIM;
    const float stab = fdec(*(volatile unsigned int*)&g_stab_bits);
    const float c1 = RATIO / (float)NSEQ;

    // one-time: zero v cols 64..87 both arrays, then ones col 64 (hi)
    for (int t = tid; t < 32 * 24; t += 288) {
        int r = t / 24, cc = 64 + t % 24;
        *(unsigned short*)(smc + SM2_VH + r * VROWB + cc * 2) = 0;
        *(unsigned short*)(smc + SM2_VL + r * VROWB + cc * 2) = 0;
    }
    __syncthreads();
    for (int t = tid; t < 32; t += 288)
        *(unsigned short*)(smc + SM2_VH + t * VROWB + 64 * 2) = 0x3F80;  // bf16 1.0

    // ldmatrix.trans lane addressing
    int a_krow = ((lid >> 4) & 1) * 8 + (lid & 7);   // k(r) row offset
    int a_mcol = ((lid >> 3) & 1) * 8;               // m col offset
    int b_krow = (lid & 7) + ((lid >> 3) & 1) * 8;   // k(r) row offset
    unsigned int aH = sb + SM2_KH + (unsigned)(a_krow * KROWB);
    unsigned int aL = sb + SM2_KL + (unsigned)(a_krow * KROWB);
    unsigned int bH = sb + SM2_VH + (unsigned)(b_krow * VROWB);
    unsigned int bL = sb + SM2_VL + (unsigned)(b_krow * VROWB);

    int mt0 = wid, mt1 = wid + 9;
    int has1 = (mt1 < 17);

    float c[2][9][4];
#pragma unroll
    for (int mi = 0; mi < 2; mi++)
#pragma unroll
        for (int nt = 0; nt < 9; nt++)
#pragma unroll
            for (int q = 0; q < 4; q++) c[mi][nt][q] = 0.f;

    for (int s = 0; s < 32; s++) {
        __syncthreads();
        {   // V tile: [32][64] coalesced -> bf16 hi/lo rows (cols 0..63)
            const float4* vsrc = (const float4*)(vbase + (size_t)s * 32 * DDIM);
            for (int t = tid; t < 512; t += 288) {
                int r = t >> 4, e4 = t & 15;
                float4 v = vsrc[t];
                unsigned int h0, l0, h1, l1;
                split2(v.x, v.y, h0, l0);
                split2(v.z, v.w, h1, l1);
                *(uint2*)(smc + SM2_VH + r * VROWB + e4 * 8) = make_uint2(h0, h1);
                *(uint2*)(smc + SM2_VL + r * VROWB + e4 * 8) = make_uint2(l0, l1);
            }
        }
        {   // kp rows with exp -> bf16 hi/lo (cols 0..271; >=266 zero)
            for (int t = tid; t < 2176; t += 288) {
                int r = t / 68, m4 = t - r * 68;
                float4 dd = *(const float4*)(dbase + (size_t)(s * 32 + r) * MPAD + m4 * 4);
                float dg = diagb[s * 32 + r] + stab;
                int m = m4 * 4;
                float4 o;
                o.x = (m + 0 < MDIM) ? c1 * (__expf(dd.x - dg) + KEPS) : 0.f;
                o.y = (m + 1 < MDIM) ? c1 * (__expf(dd.y - dg) + KEPS) : 0.f;
                o.z = (m + 2 < MDIM) ? c1 * (__expf(dd.z - dg) + KEPS) : 0.f;
                o.w = (m + 3 < MDIM) ? c1 * (__expf(dd.w - dg) + KEPS) : 0.f;
                unsigned int h0, l0, h1, l1;
                split2(o.x, o.y, h0, l0);
                split2(o.z, o.w, h1, l1);
                *(uint2*)(smc + SM2_KH + r * KROWB + m4 * 8) = make_uint2(h0, h1);
                *(uint2*)(smc + SM2_KL + r * KROWB + m4 * 8) = make_uint2(l0, l1);
            }
        }
        __syncthreads();

#pragma unroll
        for (int kk = 0; kk < 2; kk++) {
            unsigned int ka = kk * 16 * KROWB;
            unsigned int a0h[4], a0l[4], a1h[4], a1l[4];
            LDM_X4T(a0h, aH + ka + (mt0 * 16 + a_mcol) * 2);
            LDM_X4T(a0l, aL + ka + (mt0 * 16 + a_mcol) * 2);
            if (has1) {
                LDM_X4T(a1h, aH + ka + (mt1 * 16 + a_mcol) * 2);
                LDM_X4T(a1l, aL + ka + (mt1 * 16 + a_mcol) * 2);
            }
            unsigned int kb = kk * 16 * VROWB;
#pragma unroll
            for (int nt = 0; nt < 9; nt++) {
                unsigned int bh0, bh1, bl0, bl1;
                LDM_X2T(bh0, bh1, bH + kb + nt * 16);
                LDM_X2T(bl0, bl1, bL + kb + nt * 16);
                MMA_BF16(c[0][nt], a0h, bh0, bh1);
                MMA_BF16(c[0][nt], a0h, bl0, bl1);
                MMA_BF16(c[0][nt], a0l, bh0, bh1);
                if (has1) {
                    MMA_BF16(c[1][nt], a1h, bh0, bh1);
                    MMA_BF16(c[1][nt], a1h, bl0, bl1);
                    MMA_BF16(c[1][nt], a1l, bh0, bh1);
                }
            }
        }
    }

    // epilogue: atomicAdd fragments into g_CT[e][m]
    float* gCT = g_CT + (size_t)bh * EROWS * MPAD;
#pragma unroll
    for (int mi = 0; mi < 2; mi++) {
        int mt = wid + mi * 9;
        if (mt > 16) continue;
        int m0 = mt * 16 + g, m1 = m0 + 8;
#pragma unroll
        for (int nt = 0; nt < 9; nt++) {
            int e0 = nt * 8 + tc * 2;
            if (e0 < ECOLS) {
                if (m0 < MDIM) atomicAdd(&gCT[(size_t)e0 * MPAD + m0], c[mi][nt][0]);
                if (m1 < MDIM) atomicAdd(&gCT[(size_t)e0 * MPAD + m1], c[mi][nt][2]);
            }
            if (e0 + 1 < ECOLS) {
                if (m0 < MDIM) atomicAdd(&gCT[(size_t)(e0 + 1) * MPAD + m0], c[mi][nt][1]);
                if (m1 < MDIM) atomicAdd(&gCT[(size_t)(e0 + 1) * MPAD + m1], c[mi][nt][3]);
            }
        }
    }
}

// =======================================================================
// out: qp exp-transform + out = D_inv * qp @ C. (unchanged, R8-passing)
// =======================================================================
__global__ void __launch_bounds__(256, 2) out_kernel(float* __restrict__ out) {
    extern __shared__ float sm[];
    float* CsT    = sm;                       // [65][276]
    float* qp     = CsT + 65 * CTSTR;         // [32][272]
    float* stab_s = qp + 32 * MPAD;
    float* den    = stab_s + 32;
    int tid = threadIdx.x;
    int bh = blockIdx.y;
    int row0b = blockIdx.x * 128;

    {
        const float4* gCT4 = (const float4*)(g_CT + (size_t)bh * EROWS * MPAD);
        float4* CsT4 = (float4*)CsT;
        for (int i = tid; i < 65 * 68; i += 256) {
            int el = i / 68, m4 = i % 68;
            CsT4[el * 69 + m4] = gCT4[el * 68 + m4];
        }
        for (int i = tid; i < 65; i += 256)
            CsT4[i * 69 + 68] = make_float4(0.f, 0.f, 0.f, 0.f);
    }
    const float* dbase = g_qdash + ((size_t)bh * NSEQ + row0b) * MPAD;
    const float* diagb = g_qdiag + bh * NSEQ + row0b;
    float* obase = out + ((size_t)bh * NSEQ + row0b) * DDIM;

    const ulonglong2* CsU2 = (const ulonglong2*)CsT;
    const ulonglong2* qpU2 = (const ulonglong2*)qp;
    int lane = tid & 31, w = tid >> 5;
    int r0 = w * 4;

    for (int s = 0; s < 4; s++) {
        __syncthreads();
        {
            float4* qp4 = (float4*)qp;
            for (int t = tid; t < 2176; t += 256) {
                int r = t / 68, m4 = t % 68;
                qp4[r * 68 + m4] = *(const float4*)(dbase + (size_t)(s * 32 + r) * MPAD + m4 * 4);
            }
        }
        __syncthreads();
        {
            int r = tid >> 3, part = tid & 7;
            float mv = -INFINITY;
            for (int m = part; m < MDIM; m += 8) mv = fmaxf(mv, qp[r * MPAD + m]);
            mv = fmaxf(mv, __shfl_xor_sync(0xffffffffu, mv, 1));
            mv = fmaxf(mv, __shfl_xor_sync(0xffffffffu, mv, 2));
            mv = fmaxf(mv, __shfl_xor_sync(0xffffffffu, mv, 4));
            if (part == 0) stab_s[r] = mv;
        }
        __syncthreads();
        {
            int r = tid >> 3, part = tid & 7;
            float dg = diagb[s * 32 + r] + stab_s[r];
            for (int m = part; m < MPAD; m += 8) {
                float val = 0.f;
                if (m < MDIM) val = RATIO * (__expf(qp[r * MPAD + m] - dg) + KEPS);
                qp[r * MPAD + m] = val;
            }
        }
        __syncthreads();
        {
            int r = tid >> 3, part = tid & 7;
            const float* dc = CsT + 64 * CTSTR;
            float dd = 0.f;
            for (int m = part; m < MPAD; m += 8) dd += qp[r * MPAD + m] * dc[m];
            dd += __shfl_xor_sync(0xffffffffu, dd, 1);
            dd += __shfl_xor_sync(0xffffffffu, dd, 2);
            dd += __shfl_xor_sync(0xffffffffu, dd, 4);
            if (part == 0) den[r] = dd;
        }
        __syncthreads();
        {
            unsigned long long a[4][2];
#pragma unroll
            for (int j = 0; j < 4; j++) { a[j][0] = 0ULL; a[j][1] = 0ULL; }
            const ulonglong2* c0 = CsU2 + (size_t)lane * 69;
            const ulonglong2* c1 = CsU2 + (size_t)(lane + 32) * 69;
            const ulonglong2* q0 = qpU2 + (size_t)r0 * 68;
#pragma unroll 2
            for (int qd = 0; qd < 68; qd++) {
                ulonglong2 cA = c0[qd];
                ulonglong2 cB = c1[qd];
#pragma unroll
                for (int j = 0; j < 4; j++) {
                    ulonglong2 qv = q0[j * 68 + qd];
                    FMA2(a[j][0], qv.x, cA.x); FMA2(a[j][0], qv.y, cA.y);
                    FMA2(a[j][1], qv.x, cB.x); FMA2(a[j][1], qv.y, cB.y);
                }
            }
#pragma unroll
            for (int j = 0; j < 4; j++) {
                int r = r0 + j;
                float di = 1.0f / den[r];
                float* orow = obase + (size_t)(s * 32 + r) * DDIM;
                orow[lane]      = pairsum(a[j][0]) * di;
                orow[lane + 32] = pairsum(a[j][1]) * di;
            }
        }
    }
}

// =======================================================================
extern "C" void kernel_launch(void* const* d_in, const int* in_sizes, int n_in,
                              void* d_out, int out_size) {
    int pidx = -1;
    for (int i = 0; i < n_in; i++) if (in_sizes[i] == MDIM * DDIM) pidx = i;
    const float* rest[3] = {nullptr, nullptr, nullptr};
    int rc = 0;
    for (int i = 0; i < n_in && rc < 3; i++) {
        if (i == pidx) continue;
        rest[rc++] = (const float*)d_in[i];
    }
    const float* q = rest[0];
    const float* k = rest[1];
    const float* v = rest[2];
    const float* proj = (const float*)d_in[pidx];
    float* out = (float*)d_out;

    int smC = (65 * CTSTR + 32 * MPAD + 64) * (int)sizeof(float);          // ~107 KB

    cudaFuncSetAttribute(dash_mma_kernel,    cudaFuncAttributeMaxDynamicSharedMemorySize, SM_DASH_TOTAL);
    cudaFuncSetAttribute(context_mma_kernel, cudaFuncAttributeMaxDynamicSharedMemorySize, SM2_TOTAL);
    cudaFuncSetAttribute(out_kernel,         cudaFuncAttributeMaxDynamicSharedMemorySize, smC);

    init_kernel<<<512, 256>>>();
    dash_mma_kernel<<<BH * 4, 256, SM_DASH_TOTAL>>>(k, proj, 1);
    dash_mma_kernel<<<BH * 4, 256, SM_DASH_TOTAL>>>(q, proj, 0);
    context_mma_kernel<<<dim3(4, 32), 288, SM2_TOTAL>>>(v);
    out_kernel<<<dim3(32, 32), 256, smC>>>(out);
}

// round 10
// speedup vs baseline: 2.4312x; 1.1571x over previous
#include <cuda_runtime.h>
#include <cuda_bf16.h>
#include <math.h>

#define BH 32
#define NSEQ 4096
#define DDIM 64
#define MDIM 266
#define MPAD 272            // dash row stride (floats)
#define ECOLS 65
#define EROWS 68
#define CTSTR 276
#define NPAD 288            // dash mma n-dim padding
#define BROW 144            // dash bf16 smem row stride BYTES
#define NORMALIZER 0.3535533905932738f   // 64^-0.25
#define DIAGC 0.0625f                    // 0.5 * 64^-0.5
#define KEPS 1e-4f
#define RATIO 0.06131393835f             // 266^-0.5

// ---------------- f32x2 helpers ----------------
#define FMA2(acc, a, b) asm("fma.rn.f32x2 %0, %1, %2, %0;" : "+l"(acc) : "l"(a), "l"(b))
__device__ __forceinline__ float pairsum(unsigned long long v) {
    float lo, hi;
    asm("mov.b64 {%0,%1}, %2;" : "=f"(lo), "=f"(hi) : "l"(v));
    return lo + hi;
}

// ---------------- warp-mma helpers (non-'a' features) --------------
__device__ __forceinline__ unsigned int smem_u32(const void* p) {
    unsigned int a;
    asm("{ .reg .u64 t; cvta.to.shared.u64 t, %1; cvt.u32.u64 %0, t; }" : "=r"(a) : "l"(p));
    return a;
}
#define LDM_X4(d, addr) \
    asm volatile("ldmatrix.sync.aligned.m8n8.x4.shared.b16 {%0,%1,%2,%3}, [%4];" \
        : "=r"((d)[0]), "=r"((d)[1]), "=r"((d)[2]), "=r"((d)[3]) : "r"(addr))
#define LDM_X2(d0, d1, addr) \
    asm volatile("ldmatrix.sync.aligned.m8n8.x2.shared.b16 {%0,%1}, [%2];" \
        : "=r"(d0), "=r"(d1) : "r"(addr))
#define LDM_X4T(d, addr) \
    asm volatile("ldmatrix.sync.aligned.m8n8.x4.trans.shared.b16 {%0,%1,%2,%3}, [%4];" \
        : "=r"((d)[0]), "=r"((d)[1]), "=r"((d)[2]), "=r"((d)[3]) : "r"(addr))
#define LDM_X2T(d0, d1, addr) \
    asm volatile("ldmatrix.sync.aligned.m8n8.x2.trans.shared.b16 {%0,%1}, [%2];" \
        : "=r"(d0), "=r"(d1) : "r"(addr))
#define MMA_BF16(c, a, b0, b1) \
    asm volatile("mma.sync.aligned.m16n8k16.row.col.f32.bf16.bf16.f32 " \
        "{%0,%1,%2,%3}, {%4,%5,%6,%7}, {%8,%9}, {%0,%1,%2,%3};" \
        : "+f"((c)[0]), "+f"((c)[1]), "+f"((c)[2]), "+f"((c)[3]) \
        : "r"((a)[0]), "r"((a)[1]), "r"((a)[2]), "r"((a)[3]), "r"(b0), "r"(b1))

__device__ __forceinline__ void split2(float x, float y, unsigned int& hi, unsigned int& lo) {
    __nv_bfloat16 hx = __float2bfloat16(x);
    __nv_bfloat16 hy = __float2bfloat16(y);
    float rx = x - __bfloat162float(hx);
    float ry = y - __bfloat162float(hy);
    hi = ((unsigned)__bfloat16_as_ushort(hy) << 16) | (unsigned)__bfloat16_as_ushort(hx);
    lo = ((unsigned)__bfloat16_as_ushort(__float2bfloat16(ry)) << 16)
       | (unsigned)__bfloat16_as_ushort(__float2bfloat16(rx));
}

// ---------------- scratch ----------------
__device__ unsigned int g_stab_bits;
__device__ float g_CT[(size_t)BH * EROWS * MPAD];        // [bh][e][m]
__device__ float g_kdash[(size_t)BH * NSEQ * MPAD];
__device__ float g_qdash[(size_t)BH * NSEQ * MPAD];
__device__ float g_kdiag[BH * NSEQ];
__device__ float g_qdiag[BH * NSEQ];

__device__ __forceinline__ unsigned int fenc(float f) {
    unsigned int b = __float_as_uint(f);
    return (b & 0x80000000u) ? ~b : (b | 0x80000000u);
}
__device__ __forceinline__ float fdec(unsigned int u) {
    return (u & 0x80000000u) ? __uint_as_float(u & 0x7FFFFFFFu) : __uint_as_float(~u);
}

__global__ void init_kernel() {
    int i = blockIdx.x * blockDim.x + threadIdx.x;
    if (i == 0) g_stab_bits = 0u;
    int stride = gridDim.x * blockDim.x;
    for (size_t idx = i; idx < (size_t)BH * EROWS * MPAD; idx += stride) g_CT[idx] = 0.0f;
}

// =======================================================================
// dash_mma (unchanged, R8/R9-passing): dash = (NORM*X)@P^T, bf16x3 mma.
// =======================================================================
#define SM_AHI 0
#define SM_ALO (128 * BROW)
#define SM_PHI (2 * 128 * BROW)
#define SM_PLO (SM_PHI + NPAD * BROW)
#define SM_DASH_TOTAL (SM_PLO + NPAD * BROW)

__global__ void __launch_bounds__(256, 1)
dash_mma_kernel(const float* __restrict__ x, const float* __restrict__ proj, int isK) {
    extern __shared__ char smc[];
    unsigned int sb = smem_u32(smc);
    __shared__ unsigned int red;
    int tid = threadIdx.x, wid = tid >> 5, lid = tid & 31;
    int g = lid >> 2, tc = lid & 3;
    int bh = blockIdx.x >> 2, chunk = blockIdx.x & 3;
    if (tid == 0) red = 0u;

    {
        const float4* p4 = (const float4*)proj;
        for (int i = tid; i < NPAD * 16; i += 256) {
            int m = i >> 4, gg = i & 15;
            float4 v = (m < MDIM) ? p4[m * 16 + gg] : make_float4(0.f, 0.f, 0.f, 0.f);
            unsigned int h0, l0, h1, l1;
            split2(v.x, v.y, h0, l0);
            split2(v.z, v.w, h1, l1);
            *(uint2*)(smc + SM_PHI + m * BROW + gg * 8) = make_uint2(h0, h1);
            *(uint2*)(smc + SM_PLO + m * BROW + gg * 8) = make_uint2(l0, l1);
        }
    }

    const float* xbase = x + ((size_t)bh * NSEQ + chunk * 1024) * DDIM;
    float* dashp = isK ? g_kdash : g_qdash;
    float* diagp = isK ? g_kdiag : g_qdiag;
    float maxv = -INFINITY;

    int rg = wid & 3, ng = wid >> 2;
    int r0w = rg * 32;
    int a_row = ((lid >> 3) & 1) * 8 + (lid & 7);
    int a_k8  = ((lid >> 4) & 1) * 8;
    unsigned int aHi0 = sb + SM_AHI + (unsigned)((r0w + a_row) * BROW + a_k8 * 2);
    unsigned int aLo0 = aHi0 + (SM_ALO - SM_AHI);
    int b_row = lid & 7;
    int b_k8  = ((lid >> 3) & 1) * 8;
    unsigned int bHiL = sb + SM_PHI + (unsigned)(b_row * BROW + b_k8 * 2);
    unsigned int bLoL = bHiL + (SM_PLO - SM_PHI);

    for (int s = 0; s < 8; s++) {
        __syncthreads();
        {
            int row = tid >> 1, half = tid & 1;
            const float4* xsrc = (const float4*)(xbase + (size_t)s * 128 * DDIM);
            float ssum = 0.f;
#pragma unroll
            for (int j = 0; j < 8; j++) {
                float4 v = xsrc[tid * 8 + j];
                ssum += v.x * v.x + v.y * v.y + v.z * v.z + v.w * v.w;
                unsigned int h0, l0, h1, l1;
                split2(v.x * NORMALIZER, v.y * NORMALIZER, h0, l0);
                split2(v.z * NORMALIZER, v.w * NORMALIZER, h1, l1);
                int gg = half * 8 + j;
                *(uint2*)(smc + SM_AHI + row * BROW + gg * 8) = make_uint2(h0, h1);
                *(uint2*)(smc + SM_ALO + row * BROW + gg * 8) = make_uint2(l0, l1);
            }
            ssum += __shfl_xor_sync(0xffffffffu, ssum, 1);
            if (!half) diagp[(size_t)bh * NSEQ + chunk * 1024 + s * 128 + row] = DIAGC * ssum;
        }
        __syncthreads();

        float* dbase = dashp + ((size_t)bh * NSEQ + chunk * 1024 + s * 128) * MPAD;
#pragma unroll
        for (int p = 0; p < 2; p++) {
            int n0w = ng * 144 + p * 72;
            unsigned int bHiP = bHiL + (unsigned)(n0w * BROW);
            unsigned int bLoP = bLoL + (unsigned)(n0w * BROW);
            float c[2][9][4];
#pragma unroll
            for (int rb = 0; rb < 2; rb++)
#pragma unroll
                for (int nb = 0; nb < 9; nb++)
#pragma unroll
                    for (int q = 0; q < 4; q++) c[rb][nb][q] = 0.f;

#pragma unroll
            for (int kk = 0; kk < 4; kk++) {
                unsigned int ah[2][4], al[2][4];
                LDM_X4(ah[0], aHi0 + kk * 32);
                LDM_X4(ah[1], aHi0 + 16 * BROW + kk * 32);
                LDM_X4(al[0], aLo0 + kk * 32);
                LDM_X4(al[1], aLo0 + 16 * BROW + kk * 32);
#pragma unroll
                for (int nb = 0; nb < 9; nb++) {
                    unsigned int bh0, bh1, bl0, bl1;
                    LDM_X2(bh0, bh1, bHiP + nb * 8 * BROW + kk * 32);
                    LDM_X2(bl0, bl1, bLoP + nb * 8 * BROW + kk * 32);
#pragma unroll
                    for (int rb = 0; rb < 2; rb++) {
                        MMA_BF16(c[rb][nb], ah[rb], bh0, bh1);
                        MMA_BF16(c[rb][nb], ah[rb], bl0, bl1);
                        MMA_BF16(c[rb][nb], al[rb], bh0, bh1);
                    }
                }
            }
#pragma unroll
            for (int rb = 0; rb < 2; rb++) {
                int rA = r0w + rb * 16 + g;
#pragma unroll
                for (int nb = 0; nb < 9; nb++) {
                    int n = n0w + nb * 8 + tc * 2;
                    if (n < MPAD) {
                        *(float2*)(dbase + (size_t)rA * MPAD + n) =
                            make_float2(c[rb][nb][0], c[rb][nb][1]);
                        *(float2*)(dbase + (size_t)(rA + 8) * MPAD + n) =
                            make_float2(c[rb][nb][2], c[rb][nb][3]);
                    }
                    if (isK) {
                        if (n < MDIM) maxv = fmaxf(maxv, fmaxf(c[rb][nb][0], c[rb][nb][2]));
                        if (n + 1 < MDIM) maxv = fmaxf(maxv, fmaxf(c[rb][nb][1], c[rb][nb][3]));
                    }
                }
            }
        }
    }

    if (isK) {
#pragma unroll
        for (int o = 16; o; o >>= 1) maxv = fmaxf(maxv, __shfl_xor_sync(0xffffffffu, maxv, o));
        if (lid == 0) atomicMax(&red, fenc(maxv));
        __syncthreads();
        if (tid == 0) atomicMax(&g_stab_bits, red);
    }
}

// =======================================================================
// context_mma: C[m][e] = sum_r kp[r][m]*[V|1][r][e], bf16x3 mma.
// 576 threads / 18 warps, warp = ONE m16-tile (17 active). grid (4,32),
// 1024 rows per block (32 subtiles). Reversed block->data mapping so
// reads hit kdash still resident in L2 (launched right after dash K).
// =======================================================================
#define KROWB 560
#define VROWB 176
#define SM2_KH 0
#define SM2_KL 17920
#define SM2_VH 35840
#define SM2_VL 41472
#define SM2_TOTAL 47104

__global__ void __launch_bounds__(576, 1)
context_mma_kernel(const float* __restrict__ vv) {
    extern __shared__ char smc[];
    unsigned int sb = smem_u32(smc);
    int tid = threadIdx.x, wid = tid >> 5, lid = tid & 31;
    int g = lid >> 2, tc = lid & 3;
    int bh = 31 - blockIdx.y;                // reversed: last-written first
    int row0b = (3 - blockIdx.x) * 1024;

    const float* dbase = g_kdash + ((size_t)bh * NSEQ + row0b) * MPAD;
    const float* diagb = g_kdiag + bh * NSEQ + row0b;
    const float* vbase = vv + ((size_t)bh * NSEQ + row0b) * DDIM;
    const float stab = fdec(*(volatile unsigned int*)&g_stab_bits);
    const float c1 = RATIO / (float)NSEQ;

    // one-time: zero v cols 64..87 both arrays, then ones col 64 (hi)
    for (int t = tid; t < 32 * 24; t += 576) {
        int r = t / 24, cc = 64 + t % 24;
        *(unsigned short*)(smc + SM2_VH + r * VROWB + cc * 2) = 0;
        *(unsigned short*)(smc + SM2_VL + r * VROWB + cc * 2) = 0;
    }
    __syncthreads();
    for (int t = tid; t < 32; t += 576)
        *(unsigned short*)(smc + SM2_VH + t * VROWB + 64 * 2) = 0x3F80;  // bf16 1.0

    // ldmatrix.trans lane addressing
    int a_krow = ((lid >> 4) & 1) * 8 + (lid & 7);
    int a_mcol = ((lid >> 3) & 1) * 8;
    int b_krow = (lid & 7) + ((lid >> 3) & 1) * 8;
    unsigned int aH = sb + SM2_KH + (unsigned)(a_krow * KROWB);
    unsigned int aL = sb + SM2_KL + (unsigned)(a_krow * KROWB);
    unsigned int bH = sb + SM2_VH + (unsigned)(b_krow * VROWB);
    unsigned int bL = sb + SM2_VL + (unsigned)(b_krow * VROWB);

    int mt = wid;                            // one m-tile per warp
    int active = (mt < 17);

    float c[9][4];
#pragma unroll
    for (int nt = 0; nt < 9; nt++)
#pragma unroll
        for (int q = 0; q < 4; q++) c[nt][q] = 0.f;

    for (int s = 0; s < 32; s++) {
        __syncthreads();
        {   // V tile: [32][64] coalesced -> bf16 hi/lo rows (cols 0..63)
            const float4* vsrc = (const float4*)(vbase + (size_t)s * 32 * DDIM);
            for (int t = tid; t < 512; t += 576) {
                int r = t >> 4, e4 = t & 15;
                float4 v = vsrc[t];
                unsigned int h0, l0, h1, l1;
                split2(v.x, v.y, h0, l0);
                split2(v.z, v.w, h1, l1);
                *(uint2*)(smc + SM2_VH + r * VROWB + e4 * 8) = make_uint2(h0, h1);
                *(uint2*)(smc + SM2_VL + r * VROWB + e4 * 8) = make_uint2(l0, l1);
            }
        }
        {   // kp rows with exp -> bf16 hi/lo (cols 0..271; >=266 zero)
            for (int t = tid; t < 2176; t += 576) {
                int r = t / 68, m4 = t - r * 68;
                float4 dd = *(const float4*)(dbase + (size_t)(s * 32 + r) * MPAD + m4 * 4);
                float dg = diagb[s * 32 + r] + stab;
                int m = m4 * 4;
                float4 o;
                o.x = (m + 0 < MDIM) ? c1 * (__expf(dd.x - dg) + KEPS) : 0.f;
                o.y = (m + 1 < MDIM) ? c1 * (__expf(dd.y - dg) + KEPS) : 0.f;
                o.z = (m + 2 < MDIM) ? c1 * (__expf(dd.z - dg) + KEPS) : 0.f;
                o.w = (m + 3 < MDIM) ? c1 * (__expf(dd.w - dg) + KEPS) : 0.f;
                unsigned int h0, l0, h1, l1;
                split2(o.x, o.y, h0, l0);
                split2(o.z, o.w, h1, l1);
                *(uint2*)(smc + SM2_KH + r * KROWB + m4 * 8) = make_uint2(h0, h1);
                *(uint2*)(smc + SM2_KL + r * KROWB + m4 * 8) = make_uint2(l0, l1);
            }
        }
        __syncthreads();

        if (active) {
#pragma unroll
            for (int kk = 0; kk < 2; kk++) {
                unsigned int ka = kk * 16 * KROWB;
                unsigned int a0h[4], a0l[4];
                LDM_X4T(a0h, aH + ka + (mt * 16 + a_mcol) * 2);
                LDM_X4T(a0l, aL + ka + (mt * 16 + a_mcol) * 2);
                unsigned int kb = kk * 16 * VROWB;
#pragma unroll
                for (int nt = 0; nt < 9; nt++) {
                    unsigned int bh0, bh1, bl0, bl1;
                    LDM_X2T(bh0, bh1, bH + kb + nt * 16);
                    LDM_X2T(bl0, bl1, bL + kb + nt * 16);
                    MMA_BF16(c[nt], a0h, bh0, bh1);
                    MMA_BF16(c[nt], a0h, bl0, bl1);
                    MMA_BF16(c[nt], a0l, bh0, bh1);
                }
            }
        }
    }

    // epilogue: atomicAdd fragments into g_CT[e][m]
    if (active) {
        float* gCT = g_CT + (size_t)bh * EROWS * MPAD;
        int m0 = mt * 16 + g, m1 = m0 + 8;
#pragma unroll
        for (int nt = 0; nt < 9; nt++) {
            int e0 = nt * 8 + tc * 2;
            if (e0 < ECOLS) {
                if (m0 < MDIM) atomicAdd(&gCT[(size_t)e0 * MPAD + m0], c[nt][0]);
                if (m1 < MDIM) atomicAdd(&gCT[(size_t)e0 * MPAD + m1], c[nt][2]);
            }
            if (e0 + 1 < ECOLS) {
                if (m0 < MDIM) atomicAdd(&gCT[(size_t)(e0 + 1) * MPAD + m0], c[nt][1]);
                if (m1 < MDIM) atomicAdd(&gCT[(size_t)(e0 + 1) * MPAD + m1], c[nt][3]);
            }
        }
    }
}

// =======================================================================
// out: qp exp-transform + out = D_inv * qp @ C. Reversed block mapping
// (qdash L2 reuse; launched right after dash Q).
// =======================================================================
__global__ void __launch_bounds__(256, 2) out_kernel(float* __restrict__ out) {
    extern __shared__ float sm[];
    float* CsT    = sm;                       // [65][276]
    float* qp     = CsT + 65 * CTSTR;         // [32][272]
    float* stab_s = qp + 32 * MPAD;
    float* den    = stab_s + 32;
    int tid = threadIdx.x;
    int bh = 31 - blockIdx.y;                 // reversed
    int row0b = (31 - blockIdx.x) * 128;

    {
        const float4* gCT4 = (const float4*)(g_CT + (size_t)bh * EROWS * MPAD);
        float4* CsT4 = (float4*)CsT;
        for (int i = tid; i < 65 * 68; i += 256) {
            int el = i / 68, m4 = i % 68;
            CsT4[el * 69 + m4] = gCT4[el * 68 + m4];
        }
        for (int i = tid; i < 65; i += 256)
            CsT4[i * 69 + 68] = make_float4(0.f, 0.f, 0.f, 0.f);
    }
    const float* dbase = g_qdash + ((size_t)bh * NSEQ + row0b) * MPAD;
    const float* diagb = g_qdiag + bh * NSEQ + row0b;
    float* obase = out + ((size_t)bh * NSEQ + row0b) * DDIM;

    const ulonglong2* CsU2 = (const ulonglong2*)CsT;
    const ulonglong2* qpU2 = (const ulonglong2*)qp;
    int lane = tid & 31, w = tid >> 5;
    int r0 = w * 4;

    for (int s = 0; s < 4; s++) {
        __syncthreads();
        {
            float4* qp4 = (float4*)qp;
            for (int t = tid; t < 2176; t += 256) {
                int r = t / 68, m4 = t % 68;
                qp4[r * 68 + m4] = *(const float4*)(dbase + (size_t)(s * 32 + r) * MPAD + m4 * 4);
            }
        }
        __syncthreads();
        {
            int r = tid >> 3, part = tid & 7;
            float mv = -INFINITY;
            for (int m = part; m < MDIM; m += 8) mv = fmaxf(mv, qp[r * MPAD + m]);
            mv = fmaxf(mv, __shfl_xor_sync(0xffffffffu, mv, 1));
            mv = fmaxf(mv, __shfl_xor_sync(0xffffffffu, mv, 2));
            mv = fmaxf(mv, __shfl_xor_sync(0xffffffffu, mv, 4));
            if (part == 0) stab_s[r] = mv;
        }
        __syncthreads();
        {
            int r = tid >> 3, part = tid & 7;
            float dg = diagb[s * 32 + r] + stab_s[r];
            for (int m = part; m < MPAD; m += 8) {
                float val = 0.f;
                if (m < MDIM) val = RATIO * (__expf(qp[r * MPAD + m] - dg) + KEPS);
                qp[r * MPAD + m] = val;
            }
        }
        __syncthreads();
        {
            int r = tid >> 3, part = tid & 7;
            const float* dc = CsT + 64 * CTSTR;
            float dd = 0.f;
            for (int m = part; m < MPAD; m += 8) dd += qp[r * MPAD + m] * dc[m];
            dd += __shfl_xor_sync(0xffffffffu, dd, 1);
            dd += __shfl_xor_sync(0xffffffffu, dd, 2);
            dd += __shfl_xor_sync(0xffffffffu, dd, 4);
            if (part == 0) den[r] = dd;
        }
        __syncthreads();
        {
            unsigned long long a[4][2];
#pragma unroll
            for (int j = 0; j < 4; j++) { a[j][0] = 0ULL; a[j][1] = 0ULL; }
            const ulonglong2* c0 = CsU2 + (size_t)lane * 69;
            const ulonglong2* c1 = CsU2 + (size_t)(lane + 32) * 69;
            const ulonglong2* q0 = qpU2 + (size_t)r0 * 68;
#pragma unroll 2
            for (int qd = 0; qd < 68; qd++) {
                ulonglong2 cA = c0[qd];
                ulonglong2 cB = c1[qd];
#pragma unroll
                for (int j = 0; j < 4; j++) {
                    ulonglong2 qv = q0[j * 68 + qd];
                    FMA2(a[j][0], qv.x, cA.x); FMA2(a[j][0], qv.y, cA.y);
                    FMA2(a[j][1], qv.x, cB.x); FMA2(a[j][1], qv.y, cB.y);
                }
            }
#pragma unroll
            for (int j = 0; j < 4; j++) {
                int r = r0 + j;
                float di = 1.0f / den[r];
                float* orow = obase + (size_t)(s * 32 + r) * DDIM;
                orow[lane]      = pairsum(a[j][0]) * di;
                orow[lane + 32] = pairsum(a[j][1]) * di;
            }
        }
    }
}

// =======================================================================
extern "C" void kernel_launch(void* const* d_in, const int* in_sizes, int n_in,
                              void* d_out, int out_size) {
    int pidx = -1;
    for (int i = 0; i < n_in; i++) if (in_sizes[i] == MDIM * DDIM) pidx = i;
    const float* rest[3] = {nullptr, nullptr, nullptr};
    int rc = 0;
    for (int i = 0; i < n_in && rc < 3; i++) {
        if (i == pidx) continue;
        rest[rc++] = (const float*)d_in[i];
    }
    const float* q = rest[0];
    const float* k = rest[1];
    const float* v = rest[2];
    const float* proj = (const float*)d_in[pidx];
    float* out = (float*)d_out;

    int smC = (65 * CTSTR + 32 * MPAD + 64) * (int)sizeof(float);          // ~107 KB

    cudaFuncSetAttribute(dash_mma_kernel,    cudaFuncAttributeMaxDynamicSharedMemorySize, SM_DASH_TOTAL);
    cudaFuncSetAttribute(context_mma_kernel, cudaFuncAttributeMaxDynamicSharedMemorySize, SM2_TOTAL);
    cudaFuncSetAttribute(out_kernel,         cudaFuncAttributeMaxDynamicSharedMemorySize, smC);

    init_kernel<<<512, 256>>>();
    // order: each scratch tensor consumed right after production (L2 reuse)
    dash_mma_kernel<<<BH * 4, 256, SM_DASH_TOTAL>>>(k, proj, 1);
    context_mma_kernel<<<dim3(4, 32), 576, SM2_TOTAL>>>(v);
    dash_mma_kernel<<<BH * 4, 256, SM_DASH_TOTAL>>>(q, proj, 0);
    out_kernel<<<dim3(32, 32), 256, smC>>>(out);
}

// round 12
// speedup vs baseline: 2.5452x; 1.0469x over previous
#include <cuda_runtime.h>
#include <cuda_bf16.h>
#include <math.h>

#define BH 32
#define NSEQ 4096
#define DDIM 64
#define MDIM 266
#define MPAD 272            // dash row stride (floats)
#define ECOLS 65
#define EROWS 68
#define CTSTR 276
#define NPAD 288            // dash mma n-dim padding
#define BROW 144            // dash bf16 smem row stride BYTES
#define NORMALIZER 0.3535533905932738f   // 64^-0.25
#define DIAGC 0.0625f                    // 0.5 * 64^-0.5
#define KEPS 1e-4f
#define RATIO 0.06131393835f             // 266^-0.5

// ---------------- f32x2 helpers ----------------
#define FMA2(acc, a, b) asm("fma.rn.f32x2 %0, %1, %2, %0;" : "+l"(acc) : "l"(a), "l"(b))
__device__ __forceinline__ float pairsum(unsigned long long v) {
    float lo, hi;
    asm("mov.b64 {%0,%1}, %2;" : "=f"(lo), "=f"(hi) : "l"(v));
    return lo + hi;
}

// ---------------- warp-mma helpers (non-'a' features) --------------
__device__ __forceinline__ unsigned int smem_u32(const void* p) {
    unsigned int a;
    asm("{ .reg .u64 t; cvta.to.shared.u64 t, %1; cvt.u32.u64 %0, t; }" : "=r"(a) : "l"(p));
    return a;
}
#define LDM_X4(d, addr) \
    asm volatile("ldmatrix.sync.aligned.m8n8.x4.shared.b16 {%0,%1,%2,%3}, [%4];" \
        : "=r"((d)[0]), "=r"((d)[1]), "=r"((d)[2]), "=r"((d)[3]) : "r"(addr))
#define LDM_X2(d0, d1, addr) \
    asm volatile("ldmatrix.sync.aligned.m8n8.x2.shared.b16 {%0,%1}, [%2];" \
        : "=r"(d0), "=r"(d1) : "r"(addr))
#define LDM_X4T(d, addr) \
    asm volatile("ldmatrix.sync.aligned.m8n8.x4.trans.shared.b16 {%0,%1,%2,%3}, [%4];" \
        : "=r"((d)[0]), "=r"((d)[1]), "=r"((d)[2]), "=r"((d)[3]) : "r"(addr))
#define LDM_X2T(d0, d1, addr) \
    asm volatile("ldmatrix.sync.aligned.m8n8.x2.trans.shared.b16 {%0,%1}, [%2];" \
        : "=r"(d0), "=r"(d1) : "r"(addr))
#define MMA_BF16(c, a, b0, b1) \
    asm volatile("mma.sync.aligned.m16n8k16.row.col.f32.bf16.bf16.f32 " \
        "{%0,%1,%2,%3}, {%4,%5,%6,%7}, {%8,%9}, {%0,%1,%2,%3};" \
        : "+f"((c)[0]), "+f"((c)[1]), "+f"((c)[2]), "+f"((c)[3]) \
        : "r"((a)[0]), "r"((a)[1]), "r"((a)[2]), "r"((a)[3]), "r"(b0), "r"(b1))

__device__ __forceinline__ void split2(float x, float y, unsigned int& hi, unsigned int& lo) {
    __nv_bfloat16 hx = __float2bfloat16(x);
    __nv_bfloat16 hy = __float2bfloat16(y);
    float rx = x - __bfloat162float(hx);
    float ry = y - __bfloat162float(hy);
    hi = ((unsigned)__bfloat16_as_ushort(hy) << 16) | (unsigned)__bfloat16_as_ushort(hx);
    lo = ((unsigned)__bfloat16_as_ushort(__float2bfloat16(ry)) << 16)
       | (unsigned)__bfloat16_as_ushort(__float2bfloat16(rx));
}

// ---------------- scratch ----------------
__device__ unsigned int g_stab_bits;
__device__ float g_CT[(size_t)BH * EROWS * MPAD];        // [bh][e][m]
__device__ float g_kdash[(size_t)BH * NSEQ * MPAD];
__device__ float g_qdash[(size_t)BH * NSEQ * MPAD];
__device__ float g_kdiag[BH * NSEQ];
__device__ float g_qdiag[BH * NSEQ];

__device__ __forceinline__ unsigned int fenc(float f) {
    unsigned int b = __float_as_uint(f);
    return (b & 0x80000000u) ? ~b : (b | 0x80000000u);
}
__device__ __forceinline__ float fdec(unsigned int u) {
    return (u & 0x80000000u) ? __uint_as_float(u & 0x7FFFFFFFu) : __uint_as_float(~u);
}

__global__ void init_kernel() {
    int i = blockIdx.x * blockDim.x + threadIdx.x;
    if (i == 0) g_stab_bits = 0u;
    int stride = gridDim.x * blockDim.x;
    for (size_t idx = i; idx < (size_t)BH * EROWS * MPAD; idx += stride) g_CT[idx] = 0.0f;
}

// =======================================================================
// dash_mma: dash = (NORM*X)@P^T, bf16x3 mma. 512 threads / 16 warps.
// Warp (rg 0..3, ng 0..3): rows rg*32..+32, n = ng*72 (9 n8-tiles).
// rb-split: the 2 m16-tiles are processed sequentially (36 accum regs).
// grid BH*4 (1024 rows/CTA, 8 iters of 128 rows).
// =======================================================================
#define SM_AHI 0
#define SM_ALO (128 * BROW)
#define SM_PHI (2 * 128 * BROW)
#define SM_PLO (SM_PHI + NPAD * BROW)
#define SM_DASH_TOTAL (SM_PLO + NPAD * BROW)

__global__ void __launch_bounds__(512, 1)
dash_mma_kernel(const float* __restrict__ x, const float* __restrict__ proj, int isK) {
    extern __shared__ char smc[];
    unsigned int sb = smem_u32(smc);
    __shared__ unsigned int red;
    int tid = threadIdx.x, wid = tid >> 5, lid = tid & 31;
    int g = lid >> 2, tc = lid & 3;
    int bh = blockIdx.x >> 2, chunk = blockIdx.x & 3;
    if (tid == 0) red = 0u;

    {   // P split -> smem once (rows >= 266 zero)
        const float4* p4 = (const float4*)proj;
        for (int i = tid; i < NPAD * 16; i += 512) {
            int m = i >> 4, gg = i & 15;
            float4 v = (m < MDIM) ? p4[m * 16 + gg] : make_float4(0.f, 0.f, 0.f, 0.f);
            unsigned int h0, l0, h1, l1;
            split2(v.x, v.y, h0, l0);
            split2(v.z, v.w, h1, l1);
            *(uint2*)(smc + SM_PHI + m * BROW + gg * 8) = make_uint2(h0, h1);
            *(uint2*)(smc + SM_PLO + m * BROW + gg * 8) = make_uint2(l0, l1);
        }
    }

    const float* xbase = x + ((size_t)bh * NSEQ + chunk * 1024) * DDIM;
    float* dashp = isK ? g_kdash : g_qdash;
    float* diagp = isK ? g_kdiag : g_qdiag;
    float maxv = -INFINITY;

    int rg = wid & 3, ng = wid >> 2;
    int r0w = rg * 32;
    int n0w = ng * 72;
    int a_row = ((lid >> 3) & 1) * 8 + (lid & 7);
    int a_k8  = ((lid >> 4) & 1) * 8;
    int b_row = lid & 7;
    int b_k8  = ((lid >> 3) & 1) * 8;
    unsigned int bHiP = sb + SM_PHI + (unsigned)((n0w + b_row) * BROW + b_k8 * 2);
    unsigned int bLoP = bHiP + (SM_PLO - SM_PHI);

    for (int s = 0; s < 8; s++) {
        __syncthreads();
        {   // X tile: thread = (row, quarter); 4 f4 each; diag + split
            int row = tid >> 2, quarter = tid & 3;
            const float4* xsrc = (const float4*)(xbase + (size_t)s * 128 * DDIM);
            float ssum = 0.f;
#pragma unroll
            for (int j = 0; j < 4; j++) {
                float4 v = xsrc[row * 16 + quarter * 4 + j];
                ssum += v.x * v.x + v.y * v.y + v.z * v.z + v.w * v.w;
                unsigned int h0, l0, h1, l1;
                split2(v.x * NORMALIZER, v.y * NORMALIZER, h0, l0);
                split2(v.z * NORMALIZER, v.w * NORMALIZER, h1, l1);
                int gg = quarter * 4 + j;
                *(uint2*)(smc + SM_AHI + row * BROW + gg * 8) = make_uint2(h0, h1);
                *(uint2*)(smc + SM_ALO + row * BROW + gg * 8) = make_uint2(l0, l1);
            }
            ssum += __shfl_xor_sync(0xffffffffu, ssum, 1);
            ssum += __shfl_xor_sync(0xffffffffu, ssum, 2);
            if (quarter == 0)
                diagp[(size_t)bh * NSEQ + chunk * 1024 + s * 128 + row] = DIAGC * ssum;
        }
        __syncthreads();

        float* dbase = dashp + ((size_t)bh * NSEQ + chunk * 1024 + s * 128) * MPAD;
#pragma unroll
        for (int rb = 0; rb < 2; rb++) {
            unsigned int aHiR = sb + SM_AHI +
                (unsigned)((r0w + rb * 16 + a_row) * BROW + a_k8 * 2);
            unsigned int aLoR = aHiR + (SM_ALO - SM_AHI);
            float c[9][4];
#pragma unroll
            for (int nb = 0; nb < 9; nb++)
#pragma unroll
                for (int q = 0; q < 4; q++) c[nb][q] = 0.f;

#pragma unroll
            for (int kk = 0; kk < 4; kk++) {
                unsigned int ah[4], al[4];
                LDM_X4(ah, aHiR + kk * 32);
                LDM_X4(al, aLoR + kk * 32);
#pragma unroll
                for (int nb = 0; nb < 9; nb++) {
                    unsigned int bh0, bh1, bl0, bl1;
                    LDM_X2(bh0, bh1, bHiP + nb * 8 * BROW + kk * 32);
                    LDM_X2(bl0, bl1, bLoP + nb * 8 * BROW + kk * 32);
                    MMA_BF16(c[nb], ah, bh0, bh1);
                    MMA_BF16(c[nb], ah, bl0, bl1);
                    MMA_BF16(c[nb], al, bh0, bh1);
                }
            }
            int rA = r0w + rb * 16 + g;
#pragma unroll
            for (int nb = 0; nb < 9; nb++) {
                int n = n0w + nb * 8 + tc * 2;
                if (n < MPAD) {
                    *(float2*)(dbase + (size_t)rA * MPAD + n) = make_float2(c[nb][0], c[nb][1]);
                    *(float2*)(dbase + (size_t)(rA + 8) * MPAD + n) = make_float2(c[nb][2], c[nb][3]);
                }
                if (isK) {
                    if (n < MDIM) maxv = fmaxf(maxv, fmaxf(c[nb][0], c[nb][2]));
                    if (n + 1 < MDIM) maxv = fmaxf(maxv, fmaxf(c[nb][1], c[nb][3]));
                }
            }
        }
    }

    if (isK) {
#pragma unroll
        for (int o = 16; o; o >>= 1) maxv = fmaxf(maxv, __shfl_xor_sync(0xffffffffu, maxv, o));
        if (lid == 0) atomicMax(&red, fenc(maxv));
        __syncthreads();
        if (tid == 0) atomicMax(&g_stab_bits, red);
    }
}

// =======================================================================
// context_mma: C[m][e] = sum_r kp[r][m]*[V|1][r][e], bf16x3 mma.
// 576 threads / 18 warps, warp = ONE m16-tile (17 active).
// grid (8,32): 512 rows per block (16 subtiles). Reversed mapping (L2).
// =======================================================================
#define KROWB 560
#define VROWB 176
#define SM2_KH 0
#define SM2_KL 17920
#define SM2_VH 35840
#define SM2_VL 41472
#define SM2_TOTAL 47104

__global__ void __launch_bounds__(576, 1)
context_mma_kernel(const float* __restrict__ vv) {
    extern __shared__ char smc[];
    unsigned int sb = smem_u32(smc);
    int tid = threadIdx.x, wid = tid >> 5, lid = tid & 31;
    int g = lid >> 2, tc = lid & 3;
    int bh = 31 - blockIdx.y;                // reversed: last-written first
    int row0b = (7 - (int)blockIdx.x) * 512;

    const float* dbase = g_kdash + ((size_t)bh * NSEQ + row0b) * MPAD;
    const float* diagb = g_kdiag + bh * NSEQ + row0b;
    const float* vbase = vv + ((size_t)bh * NSEQ + row0b) * DDIM;
    const float stab = fdec(*(volatile unsigned int*)&g_stab_bits);
    const float c1 = RATIO / (float)NSEQ;

    for (int t = tid; t < 32 * 24; t += 576) {
        int r = t / 24, cc = 64 + t % 24;
        *(unsigned short*)(smc + SM2_VH + r * VROWB + cc * 2) = 0;
        *(unsigned short*)(smc + SM2_VL + r * VROWB + cc * 2) = 0;
    }
    __syncthreads();
    for (int t = tid; t < 32; t += 576)
        *(unsigned short*)(smc + SM2_VH + t * VROWB + 64 * 2) = 0x3F80;  // bf16 1.0

    int a_krow = ((lid >> 4) & 1) * 8 + (lid & 7);
    int a_mcol = ((lid >> 3) & 1) * 8;
    int b_krow = (lid & 7) + ((lid >> 3) & 1) * 8;
    unsigned int aH = sb + SM2_KH + (unsigned)(a_krow * KROWB);
    unsigned int aL = sb + SM2_KL + (unsigned)(a_krow * KROWB);
    unsigned int bH = sb + SM2_VH + (unsigned)(b_krow * VROWB);
    unsigned int bL = sb + SM2_VL + (unsigned)(b_krow * VROWB);

    int mt = wid;
    int active = (mt < 17);

    float c[9][4];
#pragma unroll
    for (int nt = 0; nt < 9; nt++)
#pragma unroll
        for (int q = 0; q < 4; q++) c[nt][q] = 0.f;

    for (int s = 0; s < 16; s++) {
        __syncthreads();
        {   // V tile
            const float4* vsrc = (const float4*)(vbase + (size_t)s * 32 * DDIM);
            for (int t = tid; t < 512; t += 576) {
                int r = t >> 4, e4 = t & 15;
                float4 v = vsrc[t];
                unsigned int h0, l0, h1, l1;
                split2(v.x, v.y, h0, l0);
                split2(v.z, v.w, h1, l1);
                *(uint2*)(smc + SM2_VH + r * VROWB + e4 * 8) = make_uint2(h0, h1);
                *(uint2*)(smc + SM2_VL + r * VROWB + e4 * 8) = make_uint2(l0, l1);
            }
        }
        {   // kp rows with exp -> bf16 hi/lo
            for (int t = tid; t < 2176; t += 576) {
                int r = t / 68, m4 = t - r * 68;
                float4 dd = *(const float4*)(dbase + (size_t)(s * 32 + r) * MPAD + m4 * 4);
                float dg = diagb[s * 32 + r] + stab;
                int m = m4 * 4;
                float4 o;
                o.x = (m + 0 < MDIM) ? c1 * (__expf(dd.x - dg) + KEPS) : 0.f;
                o.y = (m + 1 < MDIM) ? c1 * (__expf(dd.y - dg) + KEPS) : 0.f;
                o.z = (m + 2 < MDIM) ? c1 * (__expf(dd.z - dg) + KEPS) : 0.f;
                o.w = (m + 3 < MDIM) ? c1 * (__expf(dd.w - dg) + KEPS) : 0.f;
                unsigned int h0, l0, h1, l1;
                split2(o.x, o.y, h0, l0);
                split2(o.z, o.w, h1, l1);
                *(uint2*)(smc + SM2_KH + r * KROWB + m4 * 8) = make_uint2(h0, h1);
                *(uint2*)(smc + SM2_KL + r * KROWB + m4 * 8) = make_uint2(l0, l1);
            }
        }
        __syncthreads();

        if (active) {
#pragma unroll
            for (int kk = 0; kk < 2; kk++) {
                unsigned int ka = kk * 16 * KROWB;
                unsigned int a0h[4], a0l[4];
                LDM_X4T(a0h, aH + ka + (mt * 16 + a_mcol) * 2);
                LDM_X4T(a0l, aL + ka + (mt * 16 + a_mcol) * 2);
                unsigned int kb = kk * 16 * VROWB;
#pragma unroll
                for (int nt = 0; nt < 9; nt++) {
                    unsigned int bh0, bh1, bl0, bl1;
                    LDM_X2T(bh0, bh1, bH + kb + nt * 16);
                    LDM_X2T(bl0, bl1, bL + kb + nt * 16);
                    MMA_BF16(c[nt], a0h, bh0, bh1);
                    MMA_BF16(c[nt], a0h, bl0, bl1);
                    MMA_BF16(c[nt], a0l, bh0, bh1);
                }
            }
        }
    }

    if (active) {
        float* gCT = g_CT + (size_t)bh * EROWS * MPAD;
        int m0 = mt * 16 + g, m1 = m0 + 8;
#pragma unroll
        for (int nt = 0; nt < 9; nt++) {
            int e0 = nt * 8 + tc * 2;
            if (e0 < ECOLS) {
                if (m0 < MDIM) atomicAdd(&gCT[(size_t)e0 * MPAD + m0], c[nt][0]);
                if (m1 < MDIM) atomicAdd(&gCT[(size_t)e0 * MPAD + m1], c[nt][2]);
            }
            if (e0 + 1 < ECOLS) {
                if (m0 < MDIM) atomicAdd(&gCT[(size_t)(e0 + 1) * MPAD + m0], c[nt][1]);
                if (m1 < MDIM) atomicAdd(&gCT[(size_t)(e0 + 1) * MPAD + m1], c[nt][3]);
            }
        }
    }
}

// =======================================================================
// out: qp exp-transform + out = D_inv * qp @ C. (unchanged, passing)
// =======================================================================
__global__ void __launch_bounds__(256, 2) out_kernel(float* __restrict__ out) {
    extern __shared__ float sm[];
    float* CsT    = sm;                       // [65][276]
    float* qp     = CsT + 65 * CTSTR;         // [32][272]
    float* stab_s = qp + 32 * MPAD;
    float* den    = stab_s + 32;
    int tid = threadIdx.x;
    int bh = 31 - blockIdx.y;                 // reversed
    int row0b = (31 - (int)blockIdx.x) * 128;

    {
        const float4* gCT4 = (const float4*)(g_CT + (size_t)bh * EROWS * MPAD);
        float4* CsT4 = (float4*)CsT;
        for (int i = tid; i < 65 * 68; i += 256) {
            int el = i / 68, m4 = i % 68;
            CsT4[el * 69 + m4] = gCT4[el * 68 + m4];
        }
        for (int i = tid; i < 65; i += 256)
            CsT4[i * 69 + 68] = make_float4(0.f, 0.f, 0.f, 0.f);
    }
    const float* dbase = g_qdash + ((size_t)bh * NSEQ + row0b) * MPAD;
    const float* diagb = g_qdiag + bh * NSEQ + row0b;
    float* obase = out + ((size_t)bh * NSEQ + row0b) * DDIM;

    const ulonglong2* CsU2 = (const ulonglong2*)CsT;
    const ulonglong2* qpU2 = (const ulonglong2*)qp;
    int lane = tid & 31, w = tid >> 5;
    int r0 = w * 4;

    for (int s = 0; s < 4; s++) {
        __syncthreads();
        {
            float4* qp4 = (float4*)qp;
            for (int t = tid; t < 2176; t += 256) {
                int r = t / 68, m4 = t % 68;
                qp4[r * 68 + m4] = *(const float4*)(dbase + (size_t)(s * 32 + r) * MPAD + m4 * 4);
            }
        }
        __syncthreads();
        {
            int r = tid >> 3, part = tid & 7;
            float mv = -INFINITY;
            for (int m = part; m < MDIM; m += 8) mv = fmaxf(mv, qp[r * MPAD + m]);
            mv = fmaxf(mv, __shfl_xor_sync(0xffffffffu, mv, 1));
            mv = fmaxf(mv, __shfl_xor_sync(0xffffffffu, mv, 2));
            mv = fmaxf(mv, __shfl_xor_sync(0xffffffffu, mv, 4));
            if (part == 0) stab_s[r] = mv;
        }
        __syncthreads();
        {
            int r = tid >> 3, part = tid & 7;
            float dg = diagb[s * 32 + r] + stab_s[r];
            for (int m = part; m < MPAD; m += 8) {
                float val = 0.f;
                if (m < MDIM) val = RATIO * (__expf(qp[r * MPAD + m] - dg) + KEPS);
                qp[r * MPAD + m] = val;
            }
        }
        __syncthreads();
        {
            int r = tid >> 3, part = tid & 7;
            const float* dc = CsT + 64 * CTSTR;
            float dd = 0.f;
            for (int m = part; m < MPAD; m += 8) dd += qp[r * MPAD + m] * dc[m];
            dd += __shfl_xor_sync(0xffffffffu, dd, 1);
            dd += __shfl_xor_sync(0xffffffffu, dd, 2);
            dd += __shfl_xor_sync(0xffffffffu, dd, 4);
            if (part == 0) den[r] = dd;
        }
        __syncthreads();
        {
            unsigned long long a[4][2];
#pragma unroll
            for (int j = 0; j < 4; j++) { a[j][0] = 0ULL; a[j][1] = 0ULL; }
            const ulonglong2* c0 = CsU2 + (size_t)lane * 69;
            const ulonglong2* c1 = CsU2 + (size_t)(lane + 32) * 69;
            const ulonglong2* q0 = qpU2 + (size_t)r0 * 68;
#pragma unroll 2
            for (int qd = 0; qd < 68; qd++) {
                ulonglong2 cA = c0[qd];
                ulonglong2 cB = c1[qd];
#pragma unroll
                for (int j = 0; j < 4; j++) {
                    ulonglong2 qv = q0[j * 68 + qd];
                    FMA2(a[j][0], qv.x, cA.x); FMA2(a[j][0], qv.y, cA.y);
                    FMA2(a[j][1], qv.x, cB.x); FMA2(a[j][1], qv.y, cB.y);
                }
            }
#pragma unroll
            for (int j = 0; j < 4; j++) {
                int r = r0 + j;
                float di = 1.0f / den[r];
                float* orow = obase + (size_t)(s * 32 + r) * DDIM;
                orow[lane]      = pairsum(a[j][0]) * di;
                orow[lane + 32] = pairsum(a[j][1]) * di;
            }
        }
    }
}

// =======================================================================
extern "C" void kernel_launch(void* const* d_in, const int* in_sizes, int n_in,
                              void* d_out, int out_size) {
    int pidx = -1;
    for (int i = 0; i < n_in; i++) if (in_sizes[i] == MDIM * DDIM) pidx = i;
    const float* rest[3] = {nullptr, nullptr, nullptr};
    int rc = 0;
    for (int i = 0; i < n_in && rc < 3; i++) {
        if (i == pidx) continue;
        rest[rc++] = (const float*)d_in[i];
    }
    const float* q = rest[0];
    const float* k = rest[1];
    const float* v = rest[2];
    const float* proj = (const float*)d_in[pidx];
    float* out = (float*)d_out;

    int smC = (65 * CTSTR + 32 * MPAD + 64) * (int)sizeof(float);          // ~107 KB

    cudaFuncSetAttribute(dash_mma_kernel,    cudaFuncAttributeMaxDynamicSharedMemorySize, SM_DASH_TOTAL);
    cudaFuncSetAttribute(context_mma_kernel, cudaFuncAttributeMaxDynamicSharedMemorySize, SM2_TOTAL);
    cudaFuncSetAttribute(out_kernel,         cudaFuncAttributeMaxDynamicSharedMemorySize, smC);

    init_kernel<<<512, 256>>>();
    // order: each scratch tensor consumed right after production (L2 reuse)
    dash_mma_kernel<<<BH * 4, 512, SM_DASH_TOTAL>>>(k, proj, 1);
    context_mma_kernel<<<dim3(8, 32), 576, SM2_TOTAL>>>(v);
    dash_mma_kernel<<<BH * 4, 512, SM_DASH_TOTAL>>>(q, proj, 0);
    out_kernel<<<dim3(32, 32), 256, smC>>>(out);
}